// round 4
// baseline (speedup 1.0000x reference)
#include <cuda_runtime.h>
#include <cstddef>
#include <cstdint>

#define NPTS 100000
#define KNN 20

__device__ __forceinline__ float lrelu(float x) { return fmaxf(x, 0.2f * x); }
__device__ __forceinline__ float to_tf32(float x) {
    float r;
    asm("cvt.rna.tf32.f32 %0, %1;" : "=f"(r) : "f"(x));
    return r;
}
// D += A(16x8,row) * B(8x8,col)  tf32
__device__ __forceinline__ void mma8(float* d, const uint4& a, uint32_t b0, uint32_t b1) {
    asm volatile(
        "mma.sync.aligned.m16n8k8.row.col.f32.tf32.tf32.f32 "
        "{%0,%1,%2,%3}, {%4,%5,%6,%7}, {%8,%9}, {%0,%1,%2,%3};"
        : "+f"(d[0]), "+f"(d[1]), "+f"(d[2]), "+f"(d[3])
        : "r"(a.x), "r"(a.y), "r"(a.z), "r"(a.w), "r"(b0), "r"(b1));
}

// ======================= device scratch ================================================
__device__ int   g_idx64;
__device__ float g_w1T[3 * 3 * 64];     // [scale][c][d]
__device__ float g_w2f[3 * 8192];       // W2 B-frag layout, tf32
__device__ float g_w3f[3 * 32768];      // W3 B-frag layout, tf32
__device__ float g_sw1T[768 * 256];
__device__ float g_sw2T[256 * 128];
__device__ float g_sw3T[128 * 64];
__device__ float g_sw4T[64 * 32];
__device__ float g_feats[(size_t)NPTS * 768];

// ---------------- dtype detection: int64 indices have zero odd 32-bit words -----------
__global__ void detect_kernel(const unsigned int* __restrict__ raw) {
    __shared__ int flag;
    if (threadIdx.x == 0) flag = 0;
    __syncthreads();
    if (raw[2 * threadIdx.x + 1] != 0u) atomicOr(&flag, 1);
    __syncthreads();
    if (threadIdx.x == 0) g_idx64 = (flag == 0) ? 1 : 0;
}

// ---------------- weight prep ---------------------------------------------------------
// B-frag (m16n8k8 .col): element (k,n): lane=(n&7)*4+(k&3), reg=(k&4)>>2
__global__ void prep_kernel(const float* __restrict__ pw1, const float* __restrict__ pw2,
                            const float* __restrict__ pw3, const float* __restrict__ sw1,
                            const float* __restrict__ sw2, const float* __restrict__ sw3,
                            const float* __restrict__ sw4) {
    const int tid = blockIdx.x * blockDim.x + threadIdx.x;
    const int stride = gridDim.x * blockDim.x;
    for (int i = tid; i < 3 * 3 * 64; i += stride) {
        int s = i / 192, r = i % 192, c = r / 64, d = r % 64;
        g_w1T[i] = pw1[s * 192 + d * 3 + c];
    }
    // W2: [S][n=128][k=64] -> frag
    for (int i = tid; i < 3 * 128 * 64; i += stride) {
        int s = i >> 13, r = i & 8191, n = r >> 6, k = r & 63;
        float v = to_tf32(pw2[s * 8192 + n * 64 + k]);
        int idx = (((n >> 3) * 8 + (k >> 3)) * 32 + (n & 7) * 4 + (k & 3)) * 2 + ((k & 4) >> 2);
        g_w2f[s * 8192 + idx] = v;
    }
    // W3: [S][n=256][k=128] -> frag
    for (int i = tid; i < 3 * 256 * 128; i += stride) {
        int s = i >> 15, r = i & 32767, n = r >> 7, k = r & 127;
        float v = to_tf32(pw3[s * 32768 + n * 128 + k]);
        int idx = (((n >> 3) * 16 + (k >> 3)) * 32 + (n & 7) * 4 + (k & 3)) * 2 + ((k & 4) >> 2);
        g_w3f[s * 32768 + idx] = v;
    }
    for (int i = tid; i < 768 * 256; i += stride) {
        int k = i >> 8, d = i & 255;
        g_sw1T[i] = sw1[d * 768 + k];
    }
    for (int i = tid; i < 256 * 128; i += stride) {
        int k = i >> 7, d = i & 127;
        g_sw2T[i] = sw2[d * 256 + k];
    }
    for (int i = tid; i < 128 * 64; i += stride) {
        int k = i >> 6, d = i & 63;
        g_sw3T[i] = sw3[d * 128 + k];
    }
    for (int i = tid; i < 64 * 32; i += stride) {
        int k = i >> 5, d = i & 31;
        g_sw4T[i] = sw4[d * 64 + k];
    }
}

// ======================= patch stage: warp mma.sync tf32 ===============================
// Tile = 80 rows. H[rows][dims] = act. C[m=row][n=dim] = A(H) x B(W^T).
// smem float offsets:
#define SF_W3F 0        // 32768
#define SF_H2F 32768    // 10240
#define SF_H1F 43008    // 5120 (aliased by per-warp staging 8*528)
#define SF_NB  48128    // 320
#define SF_W1  48448    // 192
#define SF_B1  48640    // 64
#define SF_B2  48704    // 128
#define SF_TOT 48832
#define SMEM_PATCH (SF_TOT * 4)

template <int SI>
__global__ void __launch_bounds__(256) patch_kernel(
    const float* __restrict__ points, const void* __restrict__ nbr,
    const float* __restrict__ pb1, const float* __restrict__ pb2,
    const float* __restrict__ pb3) {
    constexpr int S = (SI == 0) ? 5 : (SI == 1 ? 10 : 20);
    constexpr int PTS = 80 / S;
    constexpr int NT = NPTS / PTS;

    extern __shared__ float sm[];
    float* W3F = sm + SF_W3F;
    float* H2F = sm + SF_H2F;
    float* H1F = sm + SF_H1F;
    float* NB  = sm + SF_NB;
    float* W1  = sm + SF_W1;
    float* B1  = sm + SF_B1;
    float* B2  = sm + SF_B2;

    const int t = threadIdx.x;
    const int w = t >> 5, lane = t & 31;

    // ---- CTA init ----
    {
        const float4* src = (const float4*)(g_w3f + SI * 32768);
        for (int i = t; i < 8192; i += 256) ((float4*)W3F)[i] = src[i];
        for (int i = t; i < 192; i += 256) W1[i] = g_w1T[SI * 192 + i];
        if (t < 64) B1[t] = pb1[SI * 64 + t];
        if (t < 128) B2[t] = pb2[SI * 128 + t];
    }
    const float b3v = pb3[SI * 256 + w * 32 + lane];

    // W2 slice in registers: warp w owns dims 16w..16w+15 (ntiles 2w, 2w+1)
    uint32_t bw2[8][2][2];
#pragma unroll
    for (int ks = 0; ks < 8; ks++)
#pragma unroll
        for (int nt = 0; nt < 2; nt++) {
            float2 v = *(const float2*)(g_w2f + SI * 8192 +
                                        (((2 * w + nt) * 8 + ks) * 32 + lane) * 2);
            bw2[ks][nt][0] = __float_as_uint(v.x);
            bw2[ks][nt][1] = __float_as_uint(v.y);
        }
    const int is64 = g_idx64;
    __syncthreads();

    for (int tile = blockIdx.x; tile < NT; tile += gridDim.x) {
        const int pt0 = tile * PTS;

        // ---- gather + center ----
        if (t < 80) {
            const int p = pt0 + t / S, j = t % S;
            long long gi = is64 ? ((const long long*)nbr)[p * KNN + j]
                                : (long long)((const int*)nbr)[p * KNN + j];
            const float* q = points + gi * 3;
            const float* c = points + (long long)p * 3;
            NB[t * 4 + 0] = q[0] - c[0];
            NB[t * 4 + 1] = q[1] - c[1];
            NB[t * 4 + 2] = q[2] - c[2];
        }
        __syncthreads();

        // ---- L1: 3 -> 64 scalar, write A-frag layout ----
#pragma unroll
        for (int ii = 0; ii < 20; ii++) {
            int i = t + ii * 256;  // < 5120
            int d = i & 63, r = i >> 6;
            float v = B1[d] + NB[r * 4] * W1[d] + NB[r * 4 + 1] * W1[64 + d] +
                      NB[r * 4 + 2] * W1[128 + d];
            v = to_tf32(lrelu(v));
            int mt = r >> 4, ks = d >> 3;
            int lf = ((r & 7) << 2) | (d & 3);
            int rg = ((r & 8) >> 3) | ((d & 4) >> 1);
            H1F[((mt * 8 + ks) * 32 + lf) * 4 + rg] = v;
        }
        __syncthreads();

        // ---- L2: C2[80 x 128] = H1 x W2^T (W2 in regs) ----
        float acc2[5][2][4];
#pragma unroll
        for (int mt = 0; mt < 5; mt++)
#pragma unroll
            for (int nt = 0; nt < 2; nt++)
#pragma unroll
                for (int e = 0; e < 4; e++) acc2[mt][nt][e] = 0.f;
#pragma unroll
        for (int ks = 0; ks < 8; ks++) {
#pragma unroll
            for (int mt = 0; mt < 5; mt++) {
                uint4 A = *(const uint4*)(H1F + ((mt * 8 + ks) * 32 + lane) * 4);
#pragma unroll
                for (int nt = 0; nt < 2; nt++)
                    mma8(acc2[mt][nt], A, bw2[ks][nt][0], bw2[ks][nt][1]);
            }
        }
        // L2 epilogue: bias+leaky+tf32 -> H2F (A-frag layout for L3)
#pragma unroll
        for (int mt = 0; mt < 5; mt++)
#pragma unroll
            for (int nt = 0; nt < 2; nt++)
#pragma unroll
                for (int e = 0; e < 4; e++) {
                    int m = mt * 16 + (lane >> 2) + ((e >> 1) << 3);
                    int n = w * 16 + nt * 8 + ((lane & 3) << 1) + (e & 1);
                    float v = to_tf32(lrelu(acc2[mt][nt][e] + B2[n]));
                    int ks = n >> 3;
                    int lf = ((m & 7) << 2) | (n & 3);
                    int rg = ((m & 8) >> 3) | ((n & 4) >> 1);
                    H2F[((mt * 16 + ks) * 32 + lf) * 4 + rg] = v;
                }
        __syncthreads();

        // ---- L3: C3[80 x 256] = H2 x W3^T ----
        float acc3[5][4][4];
#pragma unroll
        for (int mt = 0; mt < 5; mt++)
#pragma unroll
            for (int nt = 0; nt < 4; nt++)
#pragma unroll
                for (int e = 0; e < 4; e++) acc3[mt][nt][e] = 0.f;
#pragma unroll 4
        for (int ks = 0; ks < 16; ks++) {
            uint32_t b[4][2];
#pragma unroll
            for (int nt = 0; nt < 4; nt++) {
                float2 v = *(const float2*)(W3F + (((4 * w + nt) * 16 + ks) * 32 + lane) * 2);
                b[nt][0] = __float_as_uint(v.x);
                b[nt][1] = __float_as_uint(v.y);
            }
#pragma unroll
            for (int mt = 0; mt < 5; mt++) {
                uint4 A = *(const uint4*)(H2F + ((mt * 16 + ks) * 32 + lane) * 4);
#pragma unroll
                for (int nt = 0; nt < 4; nt++) mma8(acc3[mt][nt], A, b[nt][0], b[nt][1]);
            }
        }

        // ---- L3 epilogue: per-warp staging (stride 33) + pooled max + bias ----
        float* stg = H1F + w * 528;
        float cur = -3.4e38f;
#pragma unroll
        for (int mt = 0; mt < 5; mt++) {
            __syncwarp();
#pragma unroll
            for (int nt = 0; nt < 4; nt++)
#pragma unroll
                for (int e = 0; e < 4; e++) {
                    int mr = (lane >> 2) + ((e >> 1) << 3);
                    int nc = nt * 8 + ((lane & 3) << 1) + (e & 1);
                    stg[mr * 33 + nc] = acc3[mt][nt][e];
                }
            __syncwarp();
#pragma unroll
            for (int r = 0; r < 16; r++) {
                cur = fmaxf(cur, stg[r * 33 + lane]);
                int grow = mt * 16 + r;
                if (((grow + 1) % S) == 0) {
                    int pt = grow / S;
                    g_feats[(size_t)(pt0 + pt) * 768 + SI * 256 + w * 32 + lane] = cur + b3v;
                    cur = -3.4e38f;
                }
            }
        }
        __syncthreads();
    }
}

// ======================= shared MLP (proven fp32 version) ==============================
__global__ void __launch_bounds__(256) mlp_kernel(
    const float* __restrict__ sb1, const float* __restrict__ sb2,
    const float* __restrict__ sb3, const float* __restrict__ sb4,
    const float* __restrict__ sw5, const float* __restrict__ sb5,
    float* __restrict__ out) {
    extern __shared__ float A[];
    const int t = threadIdx.x;
    const int pt0 = blockIdx.x * 32;

    {
        const float4* src = (const float4*)(g_feats + (size_t)pt0 * 768);
        for (int i = t; i < 6144; i += 256) ((float4*)A)[i] = src[i];
    }
    __syncthreads();

    const int dg = t & 31;
    const int rg = t >> 5;
    const int r0 = rg * 4;

    float h1v[8][4];
    {
        float acc[8][4];
#pragma unroll
        for (int i = 0; i < 8; i++)
#pragma unroll
            for (int j = 0; j < 4; j++) acc[i][j] = 0.f;
#pragma unroll 4
        for (int k = 0; k < 768; k++) {
            float4 wa = *(const float4*)(g_sw1T + k * 256 + dg * 4);
            float4 wb = *(const float4*)(g_sw1T + k * 256 + 128 + dg * 4);
#pragma unroll
            for (int j = 0; j < 4; j++) {
                float a = A[(r0 + j) * 768 + k];
                acc[0][j] += wa.x * a; acc[1][j] += wa.y * a;
                acc[2][j] += wa.z * a; acc[3][j] += wa.w * a;
                acc[4][j] += wb.x * a; acc[5][j] += wb.y * a;
                acc[6][j] += wb.z * a; acc[7][j] += wb.w * a;
            }
        }
#pragma unroll
        for (int i = 0; i < 4; i++)
#pragma unroll
            for (int j = 0; j < 4; j++) {
                h1v[i][j]     = lrelu(acc[i][j] + sb1[dg * 4 + i]);
                h1v[4 + i][j] = lrelu(acc[4 + i][j] + sb1[128 + dg * 4 + i]);
            }
    }
    __syncthreads();
#pragma unroll
    for (int j = 0; j < 4; j++)
#pragma unroll
        for (int i = 0; i < 4; i++) {
            A[(r0 + j) * 256 + dg * 4 + i]       = h1v[i][j];
            A[(r0 + j) * 256 + 128 + dg * 4 + i] = h1v[4 + i][j];
        }
    __syncthreads();

    {
        float acc[4][4];
#pragma unroll
        for (int i = 0; i < 4; i++)
#pragma unroll
            for (int j = 0; j < 4; j++) acc[i][j] = 0.f;
#pragma unroll 4
        for (int k = 0; k < 256; k++) {
            float4 wv = *(const float4*)(g_sw2T + k * 128 + dg * 4);
#pragma unroll
            for (int j = 0; j < 4; j++) {
                float a = A[(r0 + j) * 256 + k];
                acc[0][j] += wv.x * a; acc[1][j] += wv.y * a;
                acc[2][j] += wv.z * a; acc[3][j] += wv.w * a;
            }
        }
#pragma unroll
        for (int j = 0; j < 4; j++)
#pragma unroll
            for (int i = 0; i < 4; i++)
                A[8192 + (r0 + j) * 128 + dg * 4 + i] = lrelu(acc[i][j] + sb2[dg * 4 + i]);
    }
    __syncwarp();

    {
        float acc[2][4];
#pragma unroll
        for (int i = 0; i < 2; i++)
#pragma unroll
            for (int j = 0; j < 4; j++) acc[i][j] = 0.f;
#pragma unroll 4
        for (int k = 0; k < 128; k++) {
            float2 wv = *(const float2*)(g_sw3T + k * 64 + dg * 2);
#pragma unroll
            for (int j = 0; j < 4; j++) {
                float a = A[8192 + (r0 + j) * 128 + k];
                acc[0][j] += wv.x * a;
                acc[1][j] += wv.y * a;
            }
        }
#pragma unroll
        for (int j = 0; j < 4; j++)
#pragma unroll
            for (int i = 0; i < 2; i++)
                A[12288 + (r0 + j) * 64 + dg * 2 + i] = lrelu(acc[i][j] + sb3[dg * 2 + i]);
    }
    __syncwarp();

    {
        float acc[4] = {0, 0, 0, 0};
#pragma unroll 8
        for (int k = 0; k < 64; k++) {
            float wv = g_sw4T[k * 32 + dg];
#pragma unroll
            for (int j = 0; j < 4; j++) acc[j] += wv * A[12288 + (r0 + j) * 64 + k];
        }
#pragma unroll
        for (int j = 0; j < 4; j++)
            A[14336 + (r0 + j) * 32 + dg] = lrelu(acc[j] + sb4[dg]);
    }
    __syncthreads();

    if (t < 32) {
        const int r = t;
        float s = sb5[0];
#pragma unroll
        for (int k = 0; k < 32; k++) s += A[14336 + r * 32 + k] * __ldg(sw5 + k);
        out[pt0 + r] = s;
    }
}

// ======================= launch ========================================================
extern "C" void kernel_launch(void* const* d_in, const int* in_sizes, int n_in,
                              void* d_out, int out_size) {
    (void)out_size;
    const int want[18] = {300000, 2000000, 576, 192, 24576, 384, 98304, 768,
                          196608, 256,    32768, 128, 8192, 64,  2048,  32, 32, 1};
    const void* ptr[18] = {};
    {
        int used[64] = {};
        for (int w = 0; w < 18; w++) {
            for (int i = 0; i < n_in && i < 64; i++) {
                if (!used[i] && in_sizes[i] == want[w]) {
                    ptr[w] = d_in[i];
                    used[i] = 1;
                    break;
                }
            }
        }
        for (int w = 0; w < 18; w++)
            if (!ptr[w] && w < n_in) ptr[w] = d_in[w];
    }

    const float* points = (const float*)ptr[0];
    const void*  nbr    = ptr[1];
    const float* pw1 = (const float*)ptr[2];
    const float* pb1 = (const float*)ptr[3];
    const float* pw2 = (const float*)ptr[4];
    const float* pb2 = (const float*)ptr[5];
    const float* pw3 = (const float*)ptr[6];
    const float* pb3 = (const float*)ptr[7];
    const float* sw1 = (const float*)ptr[8];
    const float* sb1 = (const float*)ptr[9];
    const float* sw2 = (const float*)ptr[10];
    const float* sb2 = (const float*)ptr[11];
    const float* sw3 = (const float*)ptr[12];
    const float* sb3 = (const float*)ptr[13];
    const float* sw4 = (const float*)ptr[14];
    const float* sb4 = (const float*)ptr[15];
    const float* sw5 = (const float*)ptr[16];
    const float* sb5 = (const float*)ptr[17];

    const int SMEM_B = 24576 * 4;
    cudaFuncSetAttribute(patch_kernel<0>, cudaFuncAttributeMaxDynamicSharedMemorySize, SMEM_PATCH);
    cudaFuncSetAttribute(patch_kernel<1>, cudaFuncAttributeMaxDynamicSharedMemorySize, SMEM_PATCH);
    cudaFuncSetAttribute(patch_kernel<2>, cudaFuncAttributeMaxDynamicSharedMemorySize, SMEM_PATCH);
    cudaFuncSetAttribute(mlp_kernel, cudaFuncAttributeMaxDynamicSharedMemorySize, SMEM_B);

    detect_kernel<<<1, 256>>>((const unsigned int*)nbr);
    prep_kernel<<<128, 256>>>(pw1, pw2, pw3, sw1, sw2, sw3, sw4);
    patch_kernel<0><<<152, 256, SMEM_PATCH>>>(points, nbr, pb1, pb2, pb3);
    patch_kernel<1><<<152, 256, SMEM_PATCH>>>(points, nbr, pb1, pb2, pb3);
    patch_kernel<2><<<152, 256, SMEM_PATCH>>>(points, nbr, pb1, pb2, pb3);
    mlp_kernel<<<NPTS / 32, 256, SMEM_B>>>(sb1, sb2, sb3, sb4, sw5, sb5, (float*)d_out);
}

// round 5
// speedup vs baseline: 1.3392x; 1.3392x over previous
#include <cuda_runtime.h>
#include <cstddef>
#include <cstdint>

#define NPTS 100000
#define KNN 20

__device__ __forceinline__ float lrelu(float x) { return fmaxf(x, 0.2f * x); }
__device__ __forceinline__ float to_tf32(float x) {
    float r;
    asm("cvt.rna.tf32.f32 %0, %1;" : "=f"(r) : "f"(x));
    return r;
}
__device__ __forceinline__ void mma8(float* d, const uint4& a, uint32_t b0, uint32_t b1) {
    asm volatile(
        "mma.sync.aligned.m16n8k8.row.col.f32.tf32.tf32.f32 "
        "{%0,%1,%2,%3}, {%4,%5,%6,%7}, {%8,%9}, {%0,%1,%2,%3};"
        : "+f"(d[0]), "+f"(d[1]), "+f"(d[2]), "+f"(d[3])
        : "r"(a.x), "r"(a.y), "r"(a.z), "r"(a.w), "r"(b0), "r"(b1));
}

// ======================= device scratch ================================================
__device__ int   g_idx64;
__device__ float g_w1T[3 * 3 * 64];
__device__ float g_w2f[3 * 8192];
__device__ float g_w3f[3 * 32768];
__device__ float g_sw1f[768 * 256];
__device__ float g_sw2f[256 * 128];
__device__ float g_sw3f[128 * 64];
__device__ float g_sw4T[64 * 32];
__device__ float g_feats[(size_t)NPTS * 768];

__global__ void detect_kernel(const unsigned int* __restrict__ raw) {
    __shared__ int flag;
    if (threadIdx.x == 0) flag = 0;
    __syncthreads();
    if (raw[2 * threadIdx.x + 1] != 0u) atomicOr(&flag, 1);
    __syncthreads();
    if (threadIdx.x == 0) g_idx64 = (flag == 0) ? 1 : 0;
}

// B-frag (m16n8k8 .col): (k,n) -> lane=(n&7)*4+(k&3), reg=(k&4)>>2
__global__ void prep_kernel(const float* __restrict__ pw1, const float* __restrict__ pw2,
                            const float* __restrict__ pw3, const float* __restrict__ sw1,
                            const float* __restrict__ sw2, const float* __restrict__ sw3,
                            const float* __restrict__ sw4) {
    const int tid = blockIdx.x * blockDim.x + threadIdx.x;
    const int stride = gridDim.x * blockDim.x;
    for (int i = tid; i < 3 * 3 * 64; i += stride) {
        int s = i / 192, r = i % 192, c = r / 64, d = r % 64;
        g_w1T[i] = pw1[s * 192 + d * 3 + c];
    }
    for (int i = tid; i < 3 * 128 * 64; i += stride) {
        int s = i >> 13, r = i & 8191, n = r >> 6, k = r & 63;
        float v = to_tf32(pw2[s * 8192 + n * 64 + k]);
        int idx = (((n >> 3) * 8 + (k >> 3)) * 32 + (n & 7) * 4 + (k & 3)) * 2 + ((k & 4) >> 2);
        g_w2f[s * 8192 + idx] = v;
    }
    for (int i = tid; i < 3 * 256 * 128; i += stride) {
        int s = i >> 15, r = i & 32767, n = r >> 7, k = r & 127;
        float v = to_tf32(pw3[s * 32768 + n * 128 + k]);
        int idx = (((n >> 3) * 16 + (k >> 3)) * 32 + (n & 7) * 4 + (k & 3)) * 2 + ((k & 4) >> 2);
        g_w3f[s * 32768 + idx] = v;
    }
    for (int i = tid; i < 256 * 768; i += stride) {
        int n = i / 768, k = i % 768;
        float v = to_tf32(sw1[n * 768 + k]);
        int idx = (((n >> 3) * 96 + (k >> 3)) * 32 + (n & 7) * 4 + (k & 3)) * 2 + ((k & 4) >> 2);
        g_sw1f[idx] = v;
    }
    for (int i = tid; i < 128 * 256; i += stride) {
        int n = i >> 8, k = i & 255;
        float v = to_tf32(sw2[n * 256 + k]);
        int idx = (((n >> 3) * 32 + (k >> 3)) * 32 + (n & 7) * 4 + (k & 3)) * 2 + ((k & 4) >> 2);
        g_sw2f[idx] = v;
    }
    for (int i = tid; i < 64 * 128; i += stride) {
        int n = i >> 7, k = i & 127;
        float v = to_tf32(sw3[n * 128 + k]);
        int idx = (((n >> 3) * 16 + (k >> 3)) * 32 + (n & 7) * 4 + (k & 3)) * 2 + ((k & 4) >> 2);
        g_sw3f[idx] = v;
    }
    for (int i = tid; i < 64 * 32; i += stride) {
        int k = i >> 5, d = i & 31;
        g_sw4T[i] = sw4[d * 64 + k];
    }
}

// ======================= patch stage (merged scales, 512 thr) ==========================
#define PF_W3F  0
#define PF_H2F  32768
#define PF_STG  32768   // aliases H2F (16*528 = 8448)
#define PF_POOL 41216   // 2*4096
#define PF_H1F  49408   // 5120
#define PF_NB   54528   // 320
#define PF_W1   54848
#define PF_B1   55040
#define PF_B2   55104
#define PF_B3   55232
#define PF_TOT  55488
#define SMEM_PATCH (PF_TOT * 4)

template <int SI>
__device__ __forceinline__ void patch_run(
    float* sm, int bid, int nblk,
    const float* __restrict__ points, const void* __restrict__ nbr,
    const float* __restrict__ pb1, const float* __restrict__ pb2,
    const float* __restrict__ pb3) {
    constexpr int S = (SI == 0) ? 5 : (SI == 1 ? 10 : 20);
    constexpr int PTS = 80 / S;
    constexpr int NT = NPTS / PTS;

    const int t = threadIdx.x;
    const int w = t >> 5, lane = t & 31;
    const int ng = w & 7, mg = w >> 3;
    const int nmt = mg ? 2 : 3;

    {
        const float4* src = (const float4*)(g_w3f + SI * 32768);
        float4* dst = (float4*)(sm + PF_W3F);
        for (int i = t; i < 8192; i += 512) dst[i] = src[i];
        for (int i = t; i < 192; i += 512) sm[PF_W1 + i] = g_w1T[SI * 192 + i];
        if (t < 64) sm[PF_B1 + t] = pb1[SI * 64 + t];
        if (t < 128) sm[PF_B2 + t] = pb2[SI * 128 + t];
        if (t < 256) sm[PF_B3 + t] = pb3[SI * 256 + t];
    }
    uint32_t bw2[2][8][2];
#pragma unroll
    for (int nl = 0; nl < 2; nl++)
#pragma unroll
        for (int ks = 0; ks < 8; ks++) {
            float2 v = *(const float2*)(g_w2f + SI * 8192 +
                                        (((2 * ng + nl) * 8 + ks) * 32 + lane) * 2);
            bw2[nl][ks][0] = __float_as_uint(v.x);
            bw2[nl][ks][1] = __float_as_uint(v.y);
        }
    const int is64 = g_idx64;
    __syncthreads();

    for (int tile = bid; tile < NT; tile += nblk) {
        const int pt0 = tile * PTS;

        if (t < 80) {
            const int p = pt0 + t / S, j = t % S;
            long long gi = is64 ? ((const long long*)nbr)[p * KNN + j]
                                : (long long)((const int*)nbr)[p * KNN + j];
            const float* q = points + gi * 3;
            const float* c = points + (long long)p * 3;
            sm[PF_NB + t * 4 + 0] = q[0] - c[0];
            sm[PF_NB + t * 4 + 1] = q[1] - c[1];
            sm[PF_NB + t * 4 + 2] = q[2] - c[2];
        }
        __syncthreads();

        // L1 scalar -> A-frag (NKS=8)
#pragma unroll
        for (int ii = 0; ii < 10; ii++) {
            int i = t + ii * 512;
            int d = i & 63, r = i >> 6;
            float v = sm[PF_B1 + d] + sm[PF_NB + r * 4] * sm[PF_W1 + d] +
                      sm[PF_NB + r * 4 + 1] * sm[PF_W1 + 64 + d] +
                      sm[PF_NB + r * 4 + 2] * sm[PF_W1 + 128 + d];
            v = to_tf32(lrelu(v));
            sm[PF_H1F + ((r >> 4) * 8 + (d >> 3)) * 128 + (((r & 7) << 2) | (d & 3)) * 4 +
               (((r & 8) >> 3) | ((d & 4) >> 1))] = v;
        }
        __syncthreads();

        // L2: 16 dims (ng) x parity-mts (mg)
        float acc2[3][2][4];
#pragma unroll
        for (int im = 0; im < 3; im++)
#pragma unroll
            for (int nl = 0; nl < 2; nl++)
#pragma unroll
                for (int e = 0; e < 4; e++) acc2[im][nl][e] = 0.f;
#pragma unroll
        for (int ks = 0; ks < 8; ks++)
#pragma unroll
            for (int im = 0; im < 3; im++)
                if (im < nmt) {
                    int mta = 2 * im + mg;
                    uint4 A = *(const uint4*)(sm + PF_H1F + (mta * 8 + ks) * 128 + lane * 4);
                    mma8(acc2[im][0], A, bw2[0][ks][0], bw2[0][ks][1]);
                    mma8(acc2[im][1], A, bw2[1][ks][0], bw2[1][ks][1]);
                }
        // epilogue -> H2F (A-frag NKS=16)
#pragma unroll
        for (int im = 0; im < 3; im++)
            if (im < nmt) {
                int mta = 2 * im + mg;
#pragma unroll
                for (int nl = 0; nl < 2; nl++)
#pragma unroll
                    for (int e = 0; e < 4; e++) {
                        int m = mta * 16 + (lane >> 2) + ((e >> 1) << 3);
                        int n = ng * 16 + nl * 8 + ((lane & 3) << 1) + (e & 1);
                        float v = to_tf32(lrelu(acc2[im][nl][e] + sm[PF_B2 + n]));
                        sm[PF_H2F + (mta * 16 + (n >> 3)) * 128 +
                           (((m & 7) << 2) | (n & 3)) * 4 +
                           (((m & 8) >> 3) | ((n & 4) >> 1))] = v;
                    }
            }
        __syncthreads();

        // L3: 32 dims (ng) x parity-mts
        float acc3[3][4][4];
#pragma unroll
        for (int im = 0; im < 3; im++)
#pragma unroll
            for (int nq = 0; nq < 4; nq++)
#pragma unroll
                for (int e = 0; e < 4; e++) acc3[im][nq][e] = 0.f;
#pragma unroll 4
        for (int ks = 0; ks < 16; ks++) {
            uint32_t b[4][2];
#pragma unroll
            for (int nq = 0; nq < 4; nq++) {
                float2 v = *(const float2*)(sm + PF_W3F +
                                            (((4 * ng + nq) * 16 + ks) * 32 + lane) * 2);
                b[nq][0] = __float_as_uint(v.x);
                b[nq][1] = __float_as_uint(v.y);
            }
#pragma unroll
            for (int im = 0; im < 3; im++)
                if (im < nmt) {
                    int mta = 2 * im + mg;
                    uint4 A = *(const uint4*)(sm + PF_H2F + (mta * 16 + ks) * 128 + lane * 4);
#pragma unroll
                    for (int nq = 0; nq < 4; nq++) mma8(acc3[im][nq], A, b[nq][0], b[nq][1]);
                }
        }
        __syncthreads();  // H2F dead; STG/POOL valid

#pragma unroll
        for (int ii = 0; ii < 16; ii++) sm[PF_POOL + t + ii * 512] = -3.4e38f;
        __syncthreads();

        {
            float* stg = sm + PF_STG + w * 528;
            float cur = -3.4e38f;
#pragma unroll
            for (int im = 0; im < 3; im++)
                if (im < nmt) {
                    __syncwarp();
#pragma unroll
                    for (int nq = 0; nq < 4; nq++)
#pragma unroll
                        for (int e = 0; e < 4; e++) {
                            int mr = (lane >> 2) + ((e >> 1) << 3);
                            int nc = nq * 8 + ((lane & 3) << 1) + (e & 1);
                            stg[mr * 33 + nc] = acc3[im][nq][e];
                        }
                    __syncwarp();
                    int mta = 2 * im + mg;
#pragma unroll
                    for (int r = 0; r < 16; r++) {
                        cur = fmaxf(cur, stg[r * 33 + lane]);
                        int grow = mta * 16 + r;
                        if (((grow + 1) % S) == 0 || r == 15) {
                            sm[PF_POOL + mg * 4096 + (grow / S) * 256 + ng * 32 + lane] = cur;
                            cur = -3.4e38f;
                        }
                    }
                }
        }
        __syncthreads();

#pragma unroll
        for (int ii = 0; ii < PTS / 2; ii++) {
            int idx = t + ii * 512;
            int pt = idx >> 8, d = idx & 255;
            float v = fmaxf(sm[PF_POOL + idx], sm[PF_POOL + 4096 + idx]) + sm[PF_B3 + d];
            g_feats[(size_t)(pt0 + pt) * 768 + SI * 256 + d] = v;
        }
        __syncthreads();
    }
}

__global__ void __launch_bounds__(512) patch_all_kernel(
    const float* __restrict__ points, const void* __restrict__ nbr,
    const float* __restrict__ pb1, const float* __restrict__ pb2,
    const float* __restrict__ pb3) {
    extern __shared__ float sm[];
    int b = blockIdx.x;
    if (b < 22)      patch_run<0>(sm, b,      22, points, nbr, pb1, pb2, pb3);
    else if (b < 65) patch_run<1>(sm, b - 22, 43, points, nbr, pb1, pb2, pb3);
    else             patch_run<2>(sm, b - 65, 87, points, nbr, pb1, pb2, pb3);
}

// ======================= shared MLP: tf32 mma, 64 pts/CTA ==============================
#define MF_A   0        // 8192: A-chunk; later H2F
#define MF_H1F 8192     // 16384; later H3 (64*65) + H4 (64*33)
#define MF_H3  8192
#define MF_H4  12352
#define MF_SB1 24576
#define MF_SB2 24832
#define MF_SB3 24960
#define MF_SB4 25024
#define MF_W5  25056
#define MF_W4  25088    // 2048
#define MF_TOT 27136
#define SMEM_MLP (MF_TOT * 4)

__global__ void __launch_bounds__(256, 2) mlp_kernel(
    const float* __restrict__ sb1, const float* __restrict__ sb2,
    const float* __restrict__ sb3, const float* __restrict__ sb4,
    const float* __restrict__ sw5, const float* __restrict__ sb5,
    float* __restrict__ out) {
    extern __shared__ float sm[];
    const int t = threadIdx.x;
    const int w = t >> 5, lane = t & 31;
    const int pt0 = blockIdx.x * 64;

    for (int i = t; i < 2048; i += 256) sm[MF_W4 + i] = g_sw4T[i];
    if (t < 256) sm[MF_SB1 + t] = sb1[t];
    if (t < 128) sm[MF_SB2 + t] = sb2[t];
    if (t < 64) sm[MF_SB3 + t] = sb3[t];
    if (t < 32) {
        sm[MF_SB4 + t] = sb4[t];
        sm[MF_W5 + t] = sw5[t];
    }
    __syncthreads();

    // ---- L1: 768 -> 256, 6 k-chunks ----
    float acc1[4][4][4];
#pragma unroll
    for (int mt = 0; mt < 4; mt++)
#pragma unroll
        for (int nt = 0; nt < 4; nt++)
#pragma unroll
            for (int e = 0; e < 4; e++) acc1[mt][nt][e] = 0.f;

    for (int c = 0; c < 6; c++) {
        // conflict-free gmem -> A-frag copy
#pragma unroll
        for (int ii = 0; ii < 32; ii++) {
            int i = ii * 256 + t;
            int k3 = i & 7, mb0 = (i >> 3) & 1, mb3 = (i >> 4) & 1, q = ((i >> 5) & 3) << 1;
            int fr = i >> 7, ks = fr & 15, mt = fr >> 4;
            int m = mt * 16 + q + mb0 + (mb3 << 3);
            int kk = (ks << 3) | k3;
            int p = pt0 + m;
            if (p >= NPTS) p = NPTS - 1;
            float v = to_tf32(g_feats[(size_t)p * 768 + c * 128 + kk]);
            sm[MF_A + (mt * 16 + ks) * 128 + (((m & 7) << 2) | (kk & 3)) * 4 +
               (((m & 8) >> 3) | ((kk & 4) >> 1))] = v;
        }
        __syncthreads();
#pragma unroll 4
        for (int ks = 0; ks < 16; ks++) {
            uint32_t b[4][2];
#pragma unroll
            for (int nt = 0; nt < 4; nt++) {
                float2 v = *(const float2*)(g_sw1f +
                                            (((w * 4 + nt) * 96 + c * 16 + ks) * 32 + lane) * 2);
                b[nt][0] = __float_as_uint(v.x);
                b[nt][1] = __float_as_uint(v.y);
            }
#pragma unroll
            for (int mt = 0; mt < 4; mt++) {
                uint4 A = *(const uint4*)(sm + MF_A + (mt * 16 + ks) * 128 + lane * 4);
#pragma unroll
                for (int nt = 0; nt < 4; nt++) mma8(acc1[mt][nt], A, b[nt][0], b[nt][1]);
            }
        }
        __syncthreads();
    }
    // epilogue -> H1F (A-frag NKS=32)
#pragma unroll
    for (int mt = 0; mt < 4; mt++)
#pragma unroll
        for (int nt = 0; nt < 4; nt++)
#pragma unroll
            for (int e = 0; e < 4; e++) {
                int m = mt * 16 + (lane >> 2) + ((e >> 1) << 3);
                int n = (w * 4 + nt) * 8 + ((lane & 3) << 1) + (e & 1);
                float v = to_tf32(lrelu(acc1[mt][nt][e] + sm[MF_SB1 + n]));
                sm[MF_H1F + (mt * 32 + (n >> 3)) * 128 + (((m & 7) << 2) | (n & 3)) * 4 +
                   (((m & 8) >> 3) | ((n & 4) >> 1))] = v;
            }
    __syncthreads();

    // ---- L2: 256 -> 128 (warp w owns ntiles {w, w+8}) ----
    float acc2[4][2][4];
#pragma unroll
    for (int mt = 0; mt < 4; mt++)
#pragma unroll
        for (int j = 0; j < 2; j++)
#pragma unroll
            for (int e = 0; e < 4; e++) acc2[mt][j][e] = 0.f;
#pragma unroll 4
    for (int ks = 0; ks < 32; ks++) {
        uint32_t b[2][2];
#pragma unroll
        for (int j = 0; j < 2; j++) {
            float2 v = *(const float2*)(g_sw2f + (((w + j * 8) * 32 + ks) * 32 + lane) * 2);
            b[j][0] = __float_as_uint(v.x);
            b[j][1] = __float_as_uint(v.y);
        }
#pragma unroll
        for (int mt = 0; mt < 4; mt++) {
            uint4 A = *(const uint4*)(sm + MF_H1F + (mt * 32 + ks) * 128 + lane * 4);
            mma8(acc2[mt][0], A, b[0][0], b[0][1]);
            mma8(acc2[mt][1], A, b[1][0], b[1][1]);
        }
    }
    // epilogue -> H2F at MF_A (A-frag NKS=16)
#pragma unroll
    for (int mt = 0; mt < 4; mt++)
#pragma unroll
        for (int j = 0; j < 2; j++)
#pragma unroll
            for (int e = 0; e < 4; e++) {
                int m = mt * 16 + (lane >> 2) + ((e >> 1) << 3);
                int n = (w + j * 8) * 8 + ((lane & 3) << 1) + (e & 1);
                float v = to_tf32(lrelu(acc2[mt][j][e] + sm[MF_SB2 + n]));
                sm[MF_A + (mt * 16 + (n >> 3)) * 128 + (((m & 7) << 2) | (n & 3)) * 4 +
                   (((m & 8) >> 3) | ((n & 4) >> 1))] = v;
            }
    __syncthreads();

    // ---- L3: 128 -> 64 (warp w owns ntile w) ----
    float acc3[4][4];
#pragma unroll
    for (int mt = 0; mt < 4; mt++)
#pragma unroll
        for (int e = 0; e < 4; e++) acc3[mt][e] = 0.f;
#pragma unroll 4
    for (int ks = 0; ks < 16; ks++) {
        float2 v = *(const float2*)(g_sw3f + ((w * 16 + ks) * 32 + lane) * 2);
        uint32_t b0 = __float_as_uint(v.x), b1 = __float_as_uint(v.y);
#pragma unroll
        for (int mt = 0; mt < 4; mt++) {
            uint4 A = *(const uint4*)(sm + MF_A + (mt * 16 + ks) * 128 + lane * 4);
            mma8(acc3[mt], A, b0, b1);
        }
    }
    // epilogue -> H3 row-major (stride 65), H1F dead
#pragma unroll
    for (int mt = 0; mt < 4; mt++)
#pragma unroll
        for (int e = 0; e < 4; e++) {
            int m = mt * 16 + (lane >> 2) + ((e >> 1) << 3);
            int n = w * 8 + ((lane & 3) << 1) + (e & 1);
            sm[MF_H3 + m * 65 + n] = lrelu(acc3[mt][e] + sm[MF_SB3 + n]);
        }
    __syncthreads();

    // ---- L4 scalar: 64 -> 32 ----
#pragma unroll
    for (int ii = 0; ii < 8; ii++) {
        int idx = t + ii * 256;
        int m = idx >> 5, d = idx & 31;
        float a = sm[MF_SB4 + d];
#pragma unroll 8
        for (int k = 0; k < 64; k++) a += sm[MF_H3 + m * 65 + k] * sm[MF_W4 + k * 32 + d];
        sm[MF_H4 + m * 33 + d] = lrelu(a);
    }
    __syncthreads();

    // ---- L5: 32 -> 1 ----
    if (t < 64) {
        float s = __ldg(sb5);
#pragma unroll
        for (int k = 0; k < 32; k++) s += sm[MF_H4 + t * 33 + k] * sm[MF_W5 + k];
        int p = pt0 + t;
        if (p < NPTS) out[p] = s;
    }
}

// ======================= launch ========================================================
extern "C" void kernel_launch(void* const* d_in, const int* in_sizes, int n_in,
                              void* d_out, int out_size) {
    (void)out_size;
    const int want[18] = {300000, 2000000, 576, 192, 24576, 384, 98304, 768,
                          196608, 256,    32768, 128, 8192, 64,  2048,  32, 32, 1};
    const void* ptr[18] = {};
    {
        int used[64] = {};
        for (int w = 0; w < 18; w++) {
            for (int i = 0; i < n_in && i < 64; i++) {
                if (!used[i] && in_sizes[i] == want[w]) {
                    ptr[w] = d_in[i];
                    used[i] = 1;
                    break;
                }
            }
        }
        for (int w = 0; w < 18; w++)
            if (!ptr[w] && w < n_in) ptr[w] = d_in[w];
    }

    const float* points = (const float*)ptr[0];
    const void*  nbr    = ptr[1];
    const float* pw1 = (const float*)ptr[2];
    const float* pb1 = (const float*)ptr[3];
    const float* pw2 = (const float*)ptr[4];
    const float* pb2 = (const float*)ptr[5];
    const float* pw3 = (const float*)ptr[6];
    const float* pb3 = (const float*)ptr[7];
    const float* sw1 = (const float*)ptr[8];
    const float* sb1 = (const float*)ptr[9];
    const float* sw2 = (const float*)ptr[10];
    const float* sb2 = (const float*)ptr[11];
    const float* sw3 = (const float*)ptr[12];
    const float* sb3 = (const float*)ptr[13];
    const float* sw4 = (const float*)ptr[14];
    const float* sb4 = (const float*)ptr[15];
    const float* sw5 = (const float*)ptr[16];
    const float* sb5 = (const float*)ptr[17];

    cudaFuncSetAttribute(patch_all_kernel, cudaFuncAttributeMaxDynamicSharedMemorySize,
                         SMEM_PATCH);
    cudaFuncSetAttribute(mlp_kernel, cudaFuncAttributeMaxDynamicSharedMemorySize, SMEM_MLP);

    detect_kernel<<<1, 256>>>((const unsigned int*)nbr);
    prep_kernel<<<128, 256>>>(pw1, pw2, pw3, sw1, sw2, sw3, sw4);
    patch_all_kernel<<<152, 512, SMEM_PATCH>>>(points, nbr, pb1, pb2, pb3);
    mlp_kernel<<<(NPTS + 63) / 64, 256, SMEM_MLP>>>(sb1, sb2, sb3, sb4, sw5, sb5,
                                                    (float*)d_out);
}

// round 7
// speedup vs baseline: 1.3868x; 1.0356x over previous
#include <cuda_runtime.h>
#include <cstddef>
#include <cstdint>

#define NPTS 100000
#define KNN 20
#define NEGINF -3.4e38f

__device__ __forceinline__ float lrelu(float x) { return fmaxf(x, 0.2f * x); }
__device__ __forceinline__ float to_tf32(float x) {
    float r;
    asm("cvt.rna.tf32.f32 %0, %1;" : "=f"(r) : "f"(x));
    return r;
}
__device__ __forceinline__ void mma8(float* d, const uint4& a, uint32_t b0, uint32_t b1) {
    asm volatile(
        "mma.sync.aligned.m16n8k8.row.col.f32.tf32.tf32.f32 "
        "{%0,%1,%2,%3}, {%4,%5,%6,%7}, {%8,%9}, {%0,%1,%2,%3};"
        : "+f"(d[0]), "+f"(d[1]), "+f"(d[2]), "+f"(d[3])
        : "r"(a.x), "r"(a.y), "r"(a.z), "r"(a.w), "r"(b0), "r"(b1));
}

// ======================= device scratch ================================================
__device__ int   g_idx64;
__device__ float g_w1T[3 * 3 * 64];
__device__ float g_w2f[3 * 8192];    // W2 B-frags (lane=(n&7)*4+(k&3), reg=(k&4)>>2)
__device__ float g_w3fi[3 * 32768];  // W3 B-frags, nq-pair interleaved for LDS.128
__device__ float g_sw1f[768 * 256];
__device__ float g_sw2f[256 * 128];
__device__ float g_sw3f[128 * 64];
__device__ float g_sw4T[64 * 32];
__device__ float g_feats[(size_t)NPTS * 768];

__global__ void detect_kernel(const unsigned int* __restrict__ raw) {
    __shared__ int flag;
    if (threadIdx.x == 0) flag = 0;
    __syncthreads();
    if (raw[2 * threadIdx.x + 1] != 0u) atomicOr(&flag, 1);
    __syncthreads();
    if (threadIdx.x == 0) g_idx64 = (flag == 0) ? 1 : 0;
}

__global__ void prep_kernel(const float* __restrict__ pw1, const float* __restrict__ pw2,
                            const float* __restrict__ pw3, const float* __restrict__ sw1,
                            const float* __restrict__ sw2, const float* __restrict__ sw3,
                            const float* __restrict__ sw4) {
    const int tid = blockIdx.x * blockDim.x + threadIdx.x;
    const int stride = gridDim.x * blockDim.x;
    for (int i = tid; i < 3 * 3 * 64; i += stride) {
        int s = i / 192, r = i % 192, c = r / 64, d = r % 64;
        g_w1T[i] = pw1[s * 192 + d * 3 + c];
    }
    for (int i = tid; i < 3 * 128 * 64; i += stride) {
        int s = i >> 13, r = i & 8191, n = r >> 6, k = r & 63;
        float v = to_tf32(pw2[s * 8192 + n * 64 + k]);
        int idx = (((n >> 3) * 8 + (k >> 3)) * 32 + (n & 7) * 4 + (k & 3)) * 2 + ((k & 4) >> 2);
        g_w2f[s * 8192 + idx] = v;
    }
    // W3 interleaved: [s][ng(8)][ks(16)][pair(2)][lane(32)][nip(2)][reg(2)]
    for (int i = tid; i < 3 * 256 * 128; i += stride) {
        int s = i >> 15, r = i & 32767, n = r >> 7, k = r & 127;
        float v = to_tf32(pw3[s * 32768 + n * 128 + k]);
        int ng = n >> 5, nq = (n >> 3) & 3, pair = nq >> 1, nip = nq & 1;
        int ks = k >> 3, lane = (n & 7) * 4 + (k & 3), reg = (k & 4) >> 2;
        int idx = ((((ng * 16 + ks) * 2 + pair) * 32 + lane) * 4) + nip * 2 + reg;
        g_w3fi[s * 32768 + idx] = v;
    }
    for (int i = tid; i < 256 * 768; i += stride) {
        int n = i / 768, k = i % 768;
        float v = to_tf32(sw1[n * 768 + k]);
        int idx = (((n >> 3) * 96 + (k >> 3)) * 32 + (n & 7) * 4 + (k & 3)) * 2 + ((k & 4) >> 2);
        g_sw1f[idx] = v;
    }
    for (int i = tid; i < 128 * 256; i += stride) {
        int n = i >> 8, k = i & 255;
        float v = to_tf32(sw2[n * 256 + k]);
        int idx = (((n >> 3) * 32 + (k >> 3)) * 32 + (n & 7) * 4 + (k & 3)) * 2 + ((k & 4) >> 2);
        g_sw2f[idx] = v;
    }
    for (int i = tid; i < 64 * 128; i += stride) {
        int n = i >> 7, k = i & 127;
        float v = to_tf32(sw3[n * 128 + k]);
        int idx = (((n >> 3) * 16 + (k >> 3)) * 32 + (n & 7) * 4 + (k & 3)) * 2 + ((k & 4) >> 2);
        g_sw3f[idx] = v;
    }
    for (int i = tid; i < 64 * 32; i += stride) {
        int k = i >> 5, d = i & 31;
        g_sw4T[i] = sw4[d * 64 + k];
    }
}

// ======================= patch stage: pipelined tiles ==================================
// LAYOUT FIX vs R6: POOL moved past H2F's full 10240-float extent (was overlapping by
// 1792 floats, clobbering the persistent NEGINF slots each tile).
#define PF_W3F  0        // 32768
#define PF_H2F  32768    // 10240
#define PF_STG  32768    // aliases H2F (16*528 = 8448; dead-phase aliasing only)
#define PF_POOL 43008    // 2*4096
#define PF_H1F  51200    // 5120
#define PF_NB   56320    // 320
#define PF_W1   56640    // 192
#define PF_B1   56832    // 64
#define PF_B2   56896    // 128
#define PF_B3   57024    // 256
#define PF_TOT  57280
#define SMEM_PATCH (PF_TOT * 4)

template <int SI>
__device__ __forceinline__ void patch_run(
    float* sm, int bid, int nblk,
    const float* __restrict__ points, const void* __restrict__ nbr,
    const float* __restrict__ pb1, const float* __restrict__ pb2,
    const float* __restrict__ pb3) {
    constexpr int S = (SI == 0) ? 5 : (SI == 1 ? 10 : 20);
    constexpr int PTS = 80 / S;
    constexpr int NT = NPTS / PTS;

    const int t = threadIdx.x;
    const int w = t >> 5, lane = t & 31;
    const int ng = w & 7, mg = w >> 3;
    const int nmt = mg ? 2 : 3;
    const int is64 = g_idx64;

    {  // weights / biases / pool init
        const float4* src = (const float4*)(g_w3fi + SI * 32768);
        float4* dst = (float4*)(sm + PF_W3F);
        for (int i = t; i < 8192; i += 512) dst[i] = src[i];
        for (int i = t; i < 192; i += 512) sm[PF_W1 + i] = g_w1T[SI * 192 + i];
        if (t < 64) sm[PF_B1 + t] = pb1[SI * 64 + t];
        if (t < 128) sm[PF_B2 + t] = pb2[SI * 128 + t];
        if (t < 256) sm[PF_B3 + t] = pb3[SI * 256 + t];
#pragma unroll
        for (int ii = 0; ii < 16; ii++) sm[PF_POOL + t + ii * 512] = NEGINF;
    }
    uint32_t bw2[2][8][2];
#pragma unroll
    for (int nl = 0; nl < 2; nl++)
#pragma unroll
        for (int ks = 0; ks < 8; ks++) {
            float2 v = *(const float2*)(g_w2f + SI * 8192 +
                                        (((2 * ng + nl) * 8 + ks) * 32 + lane) * 2);
            bw2[nl][ks][0] = __float_as_uint(v.x);
            bw2[nl][ks][1] = __float_as_uint(v.y);
        }
    // prologue gather (tile = bid)
    if (t < 80) {
        const int p = bid * PTS + t / S, j = t % S;
        long long gi = is64 ? ((const long long*)nbr)[(size_t)p * KNN + j]
                            : (long long)((const int*)nbr)[p * KNN + j];
        const float* q = points + gi * 3;
        const float* c = points + (long long)p * 3;
        sm[PF_NB + t * 4 + 0] = q[0] - c[0];
        sm[PF_NB + t * 4 + 1] = q[1] - c[1];
        sm[PF_NB + t * 4 + 2] = q[2] - c[2];
    }
    __syncthreads();
    // prologue L1 (tile = bid)
#pragma unroll
    for (int ii = 0; ii < 10; ii++) {
        int i = t + ii * 512;
        int d = i & 63, r = i >> 6;
        float v = sm[PF_B1 + d] + sm[PF_NB + r * 4] * sm[PF_W1 + d] +
                  sm[PF_NB + r * 4 + 1] * sm[PF_W1 + 64 + d] +
                  sm[PF_NB + r * 4 + 2] * sm[PF_W1 + 128 + d];
        v = to_tf32(lrelu(v));
        sm[PF_H1F + ((r >> 4) * 8 + (d >> 3)) * 128 + (((r & 7) << 2) | (d & 3)) * 4 +
           (((r & 8) >> 3) | ((d & 4) >> 1))] = v;
    }
    __syncthreads();

    for (int tile = bid; tile < NT; tile += nblk) {
        const int pt0 = tile * PTS;
        const bool pf = (t < 80) && (tile + nblk < NT);

        // prefetch next-tile neighbor index
        long long gi_n = 0;
        int pn = 0;
        if (pf) {
            pn = (tile + nblk) * PTS + t / S;
            int j = t % S;
            gi_n = is64 ? ((const long long*)nbr)[(size_t)pn * KNN + j]
                        : (long long)((const int*)nbr)[pn * KNN + j];
        }

        // ---- L2 mma ----
        float acc2[3][2][4];
#pragma unroll
        for (int im = 0; im < 3; im++)
#pragma unroll
            for (int nl = 0; nl < 2; nl++)
#pragma unroll
                for (int e = 0; e < 4; e++) acc2[im][nl][e] = 0.f;
#pragma unroll
        for (int ks = 0; ks < 8; ks++)
#pragma unroll
            for (int im = 0; im < 3; im++)
                if (im < nmt) {
                    int mta = 2 * im + mg;
                    uint4 A = *(const uint4*)(sm + PF_H1F + (mta * 8 + ks) * 128 + lane * 4);
                    mma8(acc2[im][0], A, bw2[0][ks][0], bw2[0][ks][1]);
                    mma8(acc2[im][1], A, bw2[1][ks][0], bw2[1][ks][1]);
                }
        // ---- L2 epilogue -> H2F ----
#pragma unroll
        for (int im = 0; im < 3; im++)
            if (im < nmt) {
                int mta = 2 * im + mg;
#pragma unroll
                for (int nl = 0; nl < 2; nl++)
#pragma unroll
                    for (int e = 0; e < 4; e++) {
                        int m = mta * 16 + (lane >> 2) + ((e >> 1) << 3);
                        int n = ng * 16 + nl * 8 + ((lane & 3) << 1) + (e & 1);
                        float v = to_tf32(lrelu(acc2[im][nl][e] + sm[PF_B2 + n]));
                        sm[PF_H2F + (mta * 16 + (n >> 3)) * 128 +
                           (((m & 7) << 2) | (n & 3)) * 4 +
                           (((m & 8) >> 3) | ((n & 4) >> 1))] = v;
                    }
            }
        __syncthreads();  // B1

        // prefetch next-tile points (hidden under L3 mma)
        float d0 = 0.f, d1 = 0.f, d2 = 0.f;
        if (pf) {
            const float* q = points + gi_n * 3;
            const float* c = points + (long long)pn * 3;
            d0 = q[0] - c[0];
            d1 = q[1] - c[1];
            d2 = q[2] - c[2];
        }

        // ---- L3 mma ----
        float acc3[3][4][4];
#pragma unroll
        for (int im = 0; im < 3; im++)
#pragma unroll
            for (int nq = 0; nq < 4; nq++)
#pragma unroll
                for (int e = 0; e < 4; e++) acc3[im][nq][e] = 0.f;
        const float4* w3v = (const float4*)(sm + PF_W3F);
#pragma unroll 4
        for (int ks = 0; ks < 16; ks++) {
            int base = ((ng * 16 + ks) * 2) * 32 + lane;
            float4 v0 = w3v[base];
            float4 v1 = w3v[base + 32];
#pragma unroll
            for (int im = 0; im < 3; im++)
                if (im < nmt) {
                    int mta = 2 * im + mg;
                    uint4 A = *(const uint4*)(sm + PF_H2F + (mta * 16 + ks) * 128 + lane * 4);
                    mma8(acc3[im][0], A, __float_as_uint(v0.x), __float_as_uint(v0.y));
                    mma8(acc3[im][1], A, __float_as_uint(v0.z), __float_as_uint(v0.w));
                    mma8(acc3[im][2], A, __float_as_uint(v1.x), __float_as_uint(v1.y));
                    mma8(acc3[im][3], A, __float_as_uint(v1.z), __float_as_uint(v1.w));
                }
        }
        __syncthreads();  // B2 (H2F dead -> STG valid)

        // ---- stage + flush partial maxes to POOL; store next-tile NB ----
        {
            float* stg = sm + PF_STG + w * 528;
            float cur = NEGINF;
#pragma unroll
            for (int im = 0; im < 3; im++)
                if (im < nmt) {
                    __syncwarp();
#pragma unroll
                    for (int nq = 0; nq < 4; nq++)
#pragma unroll
                        for (int e = 0; e < 4; e++) {
                            int mr = (lane >> 2) + ((e >> 1) << 3);
                            int nc = nq * 8 + ((lane & 3) << 1) + (e & 1);
                            stg[mr * 33 + nc] = acc3[im][nq][e];
                        }
                    __syncwarp();
                    int mta = 2 * im + mg;
#pragma unroll
                    for (int r = 0; r < 16; r++) {
                        cur = fmaxf(cur, stg[r * 33 + lane]);
                        int grow = mta * 16 + r;
                        if (((grow + 1) % S) == 0 || r == 15) {
                            sm[PF_POOL + mg * 4096 + (grow / S) * 256 + ng * 32 + lane] = cur;
                            cur = NEGINF;
                        }
                    }
                }
        }
        if (pf) {
            sm[PF_NB + t * 4 + 0] = d0;
            sm[PF_NB + t * 4 + 1] = d1;
            sm[PF_NB + t * 4 + 2] = d2;
        }
        __syncthreads();  // B3

        // ---- combine + reset POOL + write feats ----
#pragma unroll
        for (int ii = 0; ii < PTS / 2; ii++) {
            int idx = t + ii * 512;
            int pt = idx >> 8, d = idx & 255;
            float v = fmaxf(sm[PF_POOL + idx], sm[PF_POOL + 4096 + idx]) + sm[PF_B3 + d];
            sm[PF_POOL + idx] = NEGINF;
            sm[PF_POOL + 4096 + idx] = NEGINF;
            g_feats[(size_t)(pt0 + pt) * 768 + SI * 256 + d] = v;
        }
        // ---- L1 for next tile ----
        if (tile + nblk < NT) {
#pragma unroll
            for (int ii = 0; ii < 10; ii++) {
                int i = t + ii * 512;
                int d = i & 63, r = i >> 6;
                float v = sm[PF_B1 + d] + sm[PF_NB + r * 4] * sm[PF_W1 + d] +
                          sm[PF_NB + r * 4 + 1] * sm[PF_W1 + 64 + d] +
                          sm[PF_NB + r * 4 + 2] * sm[PF_W1 + 128 + d];
                v = to_tf32(lrelu(v));
                sm[PF_H1F + ((r >> 4) * 8 + (d >> 3)) * 128 + (((r & 7) << 2) | (d & 3)) * 4 +
                   (((r & 8) >> 3) | ((d & 4) >> 1))] = v;
            }
        }
        __syncthreads();  // B4
    }
}

__global__ void __launch_bounds__(512) patch_all_kernel(
    const float* __restrict__ points, const void* __restrict__ nbr,
    const float* __restrict__ pb1, const float* __restrict__ pb2,
    const float* __restrict__ pb3) {
    extern __shared__ float sm[];
    int b = blockIdx.x;
    if (b < 22)      patch_run<0>(sm, b,      22, points, nbr, pb1, pb2, pb3);
    else if (b < 65) patch_run<1>(sm, b - 22, 43, points, nbr, pb1, pb2, pb3);
    else             patch_run<2>(sm, b - 65, 87, points, nbr, pb1, pb2, pb3);
}

// ======================= shared MLP: tf32 mma (proven R5 version) ======================
#define MF_A   0
#define MF_H1F 8192
#define MF_H3  8192
#define MF_H4  12352
#define MF_SB1 24576
#define MF_SB2 24832
#define MF_SB3 24960
#define MF_SB4 25024
#define MF_W5  25056
#define MF_W4  25088
#define MF_TOT 27136
#define SMEM_MLP (MF_TOT * 4)

__global__ void __launch_bounds__(256, 2) mlp_kernel(
    const float* __restrict__ sb1, const float* __restrict__ sb2,
    const float* __restrict__ sb3, const float* __restrict__ sb4,
    const float* __restrict__ sw5, const float* __restrict__ sb5,
    float* __restrict__ out) {
    extern __shared__ float sm[];
    const int t = threadIdx.x;
    const int w = t >> 5, lane = t & 31;
    const int pt0 = blockIdx.x * 64;

    for (int i = t; i < 2048; i += 256) sm[MF_W4 + i] = g_sw4T[i];
    if (t < 256) sm[MF_SB1 + t] = sb1[t];
    if (t < 128) sm[MF_SB2 + t] = sb2[t];
    if (t < 64) sm[MF_SB3 + t] = sb3[t];
    if (t < 32) {
        sm[MF_SB4 + t] = sb4[t];
        sm[MF_W5 + t] = sw5[t];
    }
    __syncthreads();

    float acc1[4][4][4];
#pragma unroll
    for (int mt = 0; mt < 4; mt++)
#pragma unroll
        for (int nt = 0; nt < 4; nt++)
#pragma unroll
            for (int e = 0; e < 4; e++) acc1[mt][nt][e] = 0.f;

    for (int c = 0; c < 6; c++) {
#pragma unroll
        for (int ii = 0; ii < 32; ii++) {
            int i = ii * 256 + t;
            int k3 = i & 7, mb0 = (i >> 3) & 1, mb3 = (i >> 4) & 1, q = ((i >> 5) & 3) << 1;
            int fr = i >> 7, ks = fr & 15, mt = fr >> 4;
            int m = mt * 16 + q + mb0 + (mb3 << 3);
            int kk = (ks << 3) | k3;
            int p = pt0 + m;
            if (p >= NPTS) p = NPTS - 1;
            float v = to_tf32(g_feats[(size_t)p * 768 + c * 128 + kk]);
            sm[MF_A + (mt * 16 + ks) * 128 + (((m & 7) << 2) | (kk & 3)) * 4 +
               (((m & 8) >> 3) | ((kk & 4) >> 1))] = v;
        }
        __syncthreads();
#pragma unroll 4
        for (int ks = 0; ks < 16; ks++) {
            uint32_t b[4][2];
#pragma unroll
            for (int nt = 0; nt < 4; nt++) {
                float2 v = *(const float2*)(g_sw1f +
                                            (((w * 4 + nt) * 96 + c * 16 + ks) * 32 + lane) * 2);
                b[nt][0] = __float_as_uint(v.x);
                b[nt][1] = __float_as_uint(v.y);
            }
#pragma unroll
            for (int mt = 0; mt < 4; mt++) {
                uint4 A = *(const uint4*)(sm + MF_A + (mt * 16 + ks) * 128 + lane * 4);
#pragma unroll
                for (int nt = 0; nt < 4; nt++) mma8(acc1[mt][nt], A, b[nt][0], b[nt][1]);
            }
        }
        __syncthreads();
    }
#pragma unroll
    for (int mt = 0; mt < 4; mt++)
#pragma unroll
        for (int nt = 0; nt < 4; nt++)
#pragma unroll
            for (int e = 0; e < 4; e++) {
                int m = mt * 16 + (lane >> 2) + ((e >> 1) << 3);
                int n = (w * 4 + nt) * 8 + ((lane & 3) << 1) + (e & 1);
                float v = to_tf32(lrelu(acc1[mt][nt][e] + sm[MF_SB1 + n]));
                sm[MF_H1F + (mt * 32 + (n >> 3)) * 128 + (((m & 7) << 2) | (n & 3)) * 4 +
                   (((m & 8) >> 3) | ((n & 4) >> 1))] = v;
            }
    __syncthreads();

    float acc2[4][2][4];
#pragma unroll
    for (int mt = 0; mt < 4; mt++)
#pragma unroll
        for (int j = 0; j < 2; j++)
#pragma unroll
            for (int e = 0; e < 4; e++) acc2[mt][j][e] = 0.f;
#pragma unroll 4
    for (int ks = 0; ks < 32; ks++) {
        uint32_t b[2][2];
#pragma unroll
        for (int j = 0; j < 2; j++) {
            float2 v = *(const float2*)(g_sw2f + (((w + j * 8) * 32 + ks) * 32 + lane) * 2);
            b[j][0] = __float_as_uint(v.x);
            b[j][1] = __float_as_uint(v.y);
        }
#pragma unroll
        for (int mt = 0; mt < 4; mt++) {
            uint4 A = *(const uint4*)(sm + MF_H1F + (mt * 32 + ks) * 128 + lane * 4);
            mma8(acc2[mt][0], A, b[0][0], b[0][1]);
            mma8(acc2[mt][1], A, b[1][0], b[1][1]);
        }
    }
#pragma unroll
    for (int mt = 0; mt < 4; mt++)
#pragma unroll
        for (int j = 0; j < 2; j++)
#pragma unroll
            for (int e = 0; e < 4; e++) {
                int m = mt * 16 + (lane >> 2) + ((e >> 1) << 3);
                int n = (w + j * 8) * 8 + ((lane & 3) << 1) + (e & 1);
                float v = to_tf32(lrelu(acc2[mt][j][e] + sm[MF_SB2 + n]));
                sm[MF_A + (mt * 16 + (n >> 3)) * 128 + (((m & 7) << 2) | (n & 3)) * 4 +
                   (((m & 8) >> 3) | ((n & 4) >> 1))] = v;
            }
    __syncthreads();

    float acc3[4][4];
#pragma unroll
    for (int mt = 0; mt < 4; mt++)
#pragma unroll
        for (int e = 0; e < 4; e++) acc3[mt][e] = 0.f;
#pragma unroll 4
    for (int ks = 0; ks < 16; ks++) {
        float2 v = *(const float2*)(g_sw3f + ((w * 16 + ks) * 32 + lane) * 2);
        uint32_t b0 = __float_as_uint(v.x), b1 = __float_as_uint(v.y);
#pragma unroll
        for (int mt = 0; mt < 4; mt++) {
            uint4 A = *(const uint4*)(sm + MF_A + (mt * 16 + ks) * 128 + lane * 4);
            mma8(acc3[mt], A, b0, b1);
        }
    }
#pragma unroll
    for (int mt = 0; mt < 4; mt++)
#pragma unroll
        for (int e = 0; e < 4; e++) {
            int m = mt * 16 + (lane >> 2) + ((e >> 1) << 3);
            int n = w * 8 + ((lane & 3) << 1) + (e & 1);
            sm[MF_H3 + m * 65 + n] = lrelu(acc3[mt][e] + sm[MF_SB3 + n]);
        }
    __syncthreads();

#pragma unroll
    for (int ii = 0; ii < 8; ii++) {
        int idx = t + ii * 256;
        int m = idx >> 5, d = idx & 31;
        float a = sm[MF_SB4 + d];
#pragma unroll 8
        for (int k = 0; k < 64; k++) a += sm[MF_H3 + m * 65 + k] * sm[MF_W4 + k * 32 + d];
        sm[MF_H4 + m * 33 + d] = lrelu(a);
    }
    __syncthreads();

    if (t < 64) {
        float s = __ldg(sb5);
#pragma unroll
        for (int k = 0; k < 32; k++) s += sm[MF_H4 + t * 33 + k] * sm[MF_W5 + k];
        int p = pt0 + t;
        if (p < NPTS) out[p] = s;
    }
}

// ======================= launch ========================================================
extern "C" void kernel_launch(void* const* d_in, const int* in_sizes, int n_in,
                              void* d_out, int out_size) {
    (void)out_size;
    const int want[18] = {300000, 2000000, 576, 192, 24576, 384, 98304, 768,
                          196608, 256,    32768, 128, 8192, 64,  2048,  32, 32, 1};
    const void* ptr[18] = {};
    {
        int used[64] = {};
        for (int w = 0; w < 18; w++) {
            for (int i = 0; i < n_in && i < 64; i++) {
                if (!used[i] && in_sizes[i] == want[w]) {
                    ptr[w] = d_in[i];
                    used[i] = 1;
                    break;
                }
            }
        }
        for (int w = 0; w < 18; w++)
            if (!ptr[w] && w < n_in) ptr[w] = d_in[w];
    }

    const float* points = (const float*)ptr[0];
    const void*  nbr    = ptr[1];
    const float* pw1 = (const float*)ptr[2];
    const float* pb1 = (const float*)ptr[3];
    const float* pw2 = (const float*)ptr[4];
    const float* pb2 = (const float*)ptr[5];
    const float* pw3 = (const float*)ptr[6];
    const float* pb3 = (const float*)ptr[7];
    const float* sw1 = (const float*)ptr[8];
    const float* sb1 = (const float*)ptr[9];
    const float* sw2 = (const float*)ptr[10];
    const float* sb2 = (const float*)ptr[11];
    const float* sw3 = (const float*)ptr[12];
    const float* sb3 = (const float*)ptr[13];
    const float* sw4 = (const float*)ptr[14];
    const float* sb4 = (const float*)ptr[15];
    const float* sw5 = (const float*)ptr[16];
    const float* sb5 = (const float*)ptr[17];

    cudaFuncSetAttribute(patch_all_kernel, cudaFuncAttributeMaxDynamicSharedMemorySize,
                         SMEM_PATCH);
    cudaFuncSetAttribute(mlp_kernel, cudaFuncAttributeMaxDynamicSharedMemorySize, SMEM_MLP);

    detect_kernel<<<1, 256>>>((const unsigned int*)nbr);
    prep_kernel<<<128, 256>>>(pw1, pw2, pw3, sw1, sw2, sw3, sw4);
    patch_all_kernel<<<152, 512, SMEM_PATCH>>>(points, nbr, pb1, pb2, pb3);
    mlp_kernel<<<(NPTS + 63) / 64, 256, SMEM_MLP>>>(sb1, sb2, sb3, sb4, sw5, sb5,
                                                    (float*)d_out);
}

// round 8
// speedup vs baseline: 1.9275x; 1.3899x over previous
#include <cuda_runtime.h>
#include <cstddef>
#include <cstdint>

#define NPTS 100000
#define KNN 20
#define NEGINF -3.4e38f

__device__ __forceinline__ float lrelu(float x) { return fmaxf(x, 0.2f * x); }
__device__ __forceinline__ float to_tf32(float x) {
    float r;
    asm("cvt.rna.tf32.f32 %0, %1;" : "=f"(r) : "f"(x));
    return r;
}
// pack two fp32 -> bf16x2 (lo = first arg), round-to-nearest-even
__device__ __forceinline__ uint32_t packbf(float lo, float hi) {
    uint32_t r;
    asm("cvt.rn.bf16x2.f32 %0, %1, %2;" : "=r"(r) : "f"(hi), "f"(lo));
    return r;
}
// tf32 m16n8k8 (MLP only)
__device__ __forceinline__ void mma8(float* d, const uint4& a, uint32_t b0, uint32_t b1) {
    asm volatile(
        "mma.sync.aligned.m16n8k8.row.col.f32.tf32.tf32.f32 "
        "{%0,%1,%2,%3}, {%4,%5,%6,%7}, {%8,%9}, {%0,%1,%2,%3};"
        : "+f"(d[0]), "+f"(d[1]), "+f"(d[2]), "+f"(d[3])
        : "r"(a.x), "r"(a.y), "r"(a.z), "r"(a.w), "r"(b0), "r"(b1));
}
// bf16 m16n8k16 (patch)
__device__ __forceinline__ void mma16(float* d, const uint4& a, uint32_t b0, uint32_t b1) {
    asm volatile(
        "mma.sync.aligned.m16n8k16.row.col.f32.bf16.bf16.f32 "
        "{%0,%1,%2,%3}, {%4,%5,%6,%7}, {%8,%9}, {%0,%1,%2,%3};"
        : "+f"(d[0]), "+f"(d[1]), "+f"(d[2]), "+f"(d[3])
        : "r"(a.x), "r"(a.y), "r"(a.z), "r"(a.w), "r"(b0), "r"(b1));
}

// ======================= device scratch ================================================
__device__ int      g_idx64;
__device__ float    g_w1T[3 * 3 * 64];
__device__ uint32_t g_w2b[3 * 4096];    // W2 bf16 B-frags (k16): [nt(16)][ks(4)][lane][reg(2)]
__device__ uint32_t g_w3b[3 * 16384];   // W3 bf16 B-frags: [ng(8)][ks(8)][lane][nq*2+reg(8)]
__device__ float    g_sw1f[768 * 256];  // MLP tf32 frags (proven)
__device__ float    g_sw2f[256 * 128];
__device__ float    g_sw3f[128 * 64];
__device__ float    g_sw4T[64 * 32];
__device__ float    g_feats[(size_t)NPTS * 768];

__global__ void detect_kernel(const unsigned int* __restrict__ raw) {
    __shared__ int flag;
    if (threadIdx.x == 0) flag = 0;
    __syncthreads();
    if (raw[2 * threadIdx.x + 1] != 0u) atomicOr(&flag, 1);
    __syncthreads();
    if (threadIdx.x == 0) g_idx64 = (flag == 0) ? 1 : 0;
}

__global__ void prep_kernel(const float* __restrict__ pw1, const float* __restrict__ pw2,
                            const float* __restrict__ pw3, const float* __restrict__ sw1,
                            const float* __restrict__ sw2, const float* __restrict__ sw3,
                            const float* __restrict__ sw4) {
    const int tid = blockIdx.x * blockDim.x + threadIdx.x;
    const int stride = gridDim.x * blockDim.x;
    for (int i = tid; i < 3 * 3 * 64; i += stride) {
        int s = i / 192, r = i % 192, c = r / 64, d = r % 64;
        g_w1T[i] = pw1[s * 192 + d * 3 + c];
    }
    // W2 bf16 pairs: element (n,k),(n,k+1) -> one uint32
    for (int i = tid; i < 3 * 128 * 32; i += stride) {
        int s = i / 4096, r = i % 4096, n = r >> 5, k2 = r & 31, k = k2 * 2;
        float v0 = pw2[s * 8192 + n * 64 + k];
        float v1 = pw2[s * 8192 + n * 64 + k + 1];
        int idx = (((n >> 3) * 4 + (k2 >> 3)) * 32 + (n & 7) * 4 + (k2 & 3)) * 2 +
                  ((k2 >> 2) & 1);
        g_w2b[s * 4096 + idx] = packbf(v0, v1);
    }
    // W3 bf16 pairs, nq-interleaved for LDS.128
    for (int i = tid; i < 3 * 256 * 64; i += stride) {
        int s = i >> 14, r = i & 16383, n = r >> 6, k2 = r & 63, k = k2 * 2;
        float v0 = pw3[s * 32768 + n * 128 + k];
        float v1 = pw3[s * 32768 + n * 128 + k + 1];
        int ng = n >> 5, nq = (n >> 3) & 3;
        int ks = k2 >> 3, reg = (k2 >> 2) & 1, lane = (n & 7) * 4 + (k2 & 3);
        int idx = ((ng * 8 + ks) * 32 + lane) * 8 + nq * 2 + reg;
        g_w3b[s * 16384 + idx] = packbf(v0, v1);
    }
    // MLP tf32 frags (unchanged)
    for (int i = tid; i < 256 * 768; i += stride) {
        int n = i / 768, k = i % 768;
        float v = to_tf32(sw1[n * 768 + k]);
        int idx = (((n >> 3) * 96 + (k >> 3)) * 32 + (n & 7) * 4 + (k & 3)) * 2 + ((k & 4) >> 2);
        g_sw1f[idx] = v;
    }
    for (int i = tid; i < 128 * 256; i += stride) {
        int n = i >> 8, k = i & 255;
        float v = to_tf32(sw2[n * 256 + k]);
        int idx = (((n >> 3) * 32 + (k >> 3)) * 32 + (n & 7) * 4 + (k & 3)) * 2 + ((k & 4) >> 2);
        g_sw2f[idx] = v;
    }
    for (int i = tid; i < 64 * 128; i += stride) {
        int n = i >> 7, k = i & 127;
        float v = to_tf32(sw3[n * 128 + k]);
        int idx = (((n >> 3) * 16 + (k >> 3)) * 32 + (n & 7) * 4 + (k & 3)) * 2 + ((k & 4) >> 2);
        g_sw3f[idx] = v;
    }
    for (int i = tid; i < 64 * 32; i += stride) {
        int k = i >> 5, d = i & 31;
        g_sw4T[i] = sw4[d * 64 + k];
    }
}

// ======================= patch stage: bf16 m16n8k16, pipelined =========================
// word offsets (uint32 units)
#define PF_W3F  0        // 16384 (64KB)
#define PF_H2F  16384    // 5120 uint32 (A-frags for L3)
#define PF_STG  16384    // aliases H2F region (16*528 = 8448; dead-phase only)
#define PF_POOL 24832    // 2*4096 fp32
#define PF_H1F  33024    // 2560 uint32
#define PF_NB   35584    // 320 fp32
#define PF_W1   35904    // 192
#define PF_B1   36096    // 64
#define PF_B2   36160    // 128
#define PF_B3   36288    // 256
#define PF_TOT  36544
#define SMEM_PATCH (PF_TOT * 4)

template <int SI>
__device__ __forceinline__ void patch_run(
    float* sm, int bid, int nblk,
    const float* __restrict__ points, const void* __restrict__ nbr,
    const float* __restrict__ pb1, const float* __restrict__ pb2,
    const float* __restrict__ pb3) {
    constexpr int S = (SI == 0) ? 5 : (SI == 1 ? 10 : 20);
    constexpr int PTS = 80 / S;
    constexpr int NT = NPTS / PTS;

    uint32_t* smu = (uint32_t*)sm;
    const int t = threadIdx.x;
    const int w = t >> 5, lane = t & 31;
    const int ng = w & 7, mg = w >> 3;
    const int nmt = mg ? 2 : 3;
    const int is64 = g_idx64;

    {  // weights / biases / pool init
        const uint4* src = (const uint4*)g_w3b + SI * 4096;
        uint4* dst = (uint4*)(smu + PF_W3F);
        for (int i = t; i < 4096; i += 512) dst[i] = src[i];
        for (int i = t; i < 192; i += 512) sm[PF_W1 + i] = g_w1T[SI * 192 + i];
        if (t < 64) sm[PF_B1 + t] = pb1[SI * 64 + t];
        if (t < 128) sm[PF_B2 + t] = pb2[SI * 128 + t];
        if (t < 256) sm[PF_B3 + t] = pb3[SI * 256 + t];
#pragma unroll
        for (int ii = 0; ii < 16; ii++) sm[PF_POOL + t + ii * 512] = NEGINF;
    }
    // W2 B-frags in regs: warp owns dims ng*16..+15 (nt = 2ng, 2ng+1), k16 steps = 4
    uint32_t bw2[2][4][2];
#pragma unroll
    for (int nl = 0; nl < 2; nl++)
#pragma unroll
        for (int ks = 0; ks < 4; ks++) {
            uint2 v = *(const uint2*)(g_w2b + SI * 4096 +
                                      (((2 * ng + nl) * 4 + ks) * 32 + lane) * 2);
            bw2[nl][ks][0] = v.x;
            bw2[nl][ks][1] = v.y;
        }
    // per-thread L2 biases (n even/odd of this thread's column pair)
    float b2e[2], b2o[2];
#pragma unroll
    for (int nl = 0; nl < 2; nl++) {
        int n0 = ng * 16 + nl * 8 + (lane & 3) * 2;
        b2e[nl] = pb2[SI * 128 + n0];
        b2o[nl] = pb2[SI * 128 + n0 + 1];
    }
    // prologue gather
    if (t < 80) {
        const int p = bid * PTS + t / S, j = t % S;
        long long gi = is64 ? ((const long long*)nbr)[(size_t)p * KNN + j]
                            : (long long)((const int*)nbr)[p * KNN + j];
        const float* q = points + gi * 3;
        const float* c = points + (long long)p * 3;
        sm[PF_NB + t * 4 + 0] = q[0] - c[0];
        sm[PF_NB + t * 4 + 1] = q[1] - c[1];
        sm[PF_NB + t * 4 + 2] = q[2] - c[2];
    }
    __syncthreads();
    // prologue L1 -> H1F bf16 pairs (A-frag k16 layout)
#pragma unroll
    for (int ii = 0; ii < 5; ii++) {
        int i = t + ii * 512;  // < 2560
        int d2 = i & 31, r = i >> 5, d = d2 * 2;
        float v0 = sm[PF_B1 + d] + sm[PF_NB + r * 4] * sm[PF_W1 + d] +
                   sm[PF_NB + r * 4 + 1] * sm[PF_W1 + 64 + d] +
                   sm[PF_NB + r * 4 + 2] * sm[PF_W1 + 128 + d];
        float v1 = sm[PF_B1 + d + 1] + sm[PF_NB + r * 4] * sm[PF_W1 + d + 1] +
                   sm[PF_NB + r * 4 + 1] * sm[PF_W1 + 64 + d + 1] +
                   sm[PF_NB + r * 4 + 2] * sm[PF_W1 + 128 + d + 1];
        smu[PF_H1F + ((r >> 4) * 4 + (d2 >> 3)) * 128 + ((r & 7) * 4 + (d2 & 3)) * 4 +
            (((r & 8) >> 3) | ((d2 & 4) >> 1))] = packbf(lrelu(v0), lrelu(v1));
    }
    __syncthreads();

    for (int tile = bid; tile < NT; tile += nblk) {
        const int pt0 = tile * PTS;
        const bool pf = (t < 80) && (tile + nblk < NT);

        long long gi_n = 0;
        int pn = 0;
        if (pf) {
            pn = (tile + nblk) * PTS + t / S;
            int j = t % S;
            gi_n = is64 ? ((const long long*)nbr)[(size_t)pn * KNN + j]
                        : (long long)((const int*)nbr)[pn * KNN + j];
        }

        // ---- L2 mma (bf16, K=64 -> 4 ksteps) ----
        float acc2[3][2][4];
#pragma unroll
        for (int im = 0; im < 3; im++)
#pragma unroll
            for (int nl = 0; nl < 2; nl++)
#pragma unroll
                for (int e = 0; e < 4; e++) acc2[im][nl][e] = 0.f;
        const uint4* h1u4 = (const uint4*)(smu + PF_H1F);
#pragma unroll
        for (int ks = 0; ks < 4; ks++)
#pragma unroll
            for (int im = 0; im < 3; im++)
                if (im < nmt) {
                    int mta = 2 * im + mg;
                    uint4 A = h1u4[(mta * 4 + ks) * 32 + lane];
                    mma16(acc2[im][0], A, bw2[0][ks][0], bw2[0][ks][1]);
                    mma16(acc2[im][1], A, bw2[1][ks][0], bw2[1][ks][1]);
                }
        // ---- L2 epilogue -> H2F (bf16 A-frags for L3; one STS.128 per im) ----
        {
            uint4* h2u4 = (uint4*)(smu + PF_H2F);
#pragma unroll
            for (int im = 0; im < 3; im++)
                if (im < nmt) {
                    int mta = 2 * im + mg;
                    uint4 v;
                    v.x = packbf(lrelu(acc2[im][0][0] + b2e[0]), lrelu(acc2[im][0][1] + b2o[0]));
                    v.y = packbf(lrelu(acc2[im][0][2] + b2e[0]), lrelu(acc2[im][0][3] + b2o[0]));
                    v.z = packbf(lrelu(acc2[im][1][0] + b2e[1]), lrelu(acc2[im][1][1] + b2o[1]));
                    v.w = packbf(lrelu(acc2[im][1][2] + b2e[1]), lrelu(acc2[im][1][3] + b2o[1]));
                    h2u4[(mta * 8 + ng) * 32 + lane] = v;
                }
        }
        __syncthreads();  // B1

        float d0 = 0.f, d1 = 0.f, d2 = 0.f;
        if (pf) {
            const float* q = points + gi_n * 3;
            const float* c = points + (long long)pn * 3;
            d0 = q[0] - c[0];
            d1 = q[1] - c[1];
            d2 = q[2] - c[2];
        }

        // ---- L3 mma (bf16, K=128 -> 8 ksteps) ----
        float acc3[3][4][4];
#pragma unroll
        for (int im = 0; im < 3; im++)
#pragma unroll
            for (int nq = 0; nq < 4; nq++)
#pragma unroll
                for (int e = 0; e < 4; e++) acc3[im][nq][e] = 0.f;
        const uint4* w3u4 = (const uint4*)(smu + PF_W3F);
        const uint4* h2u4 = (const uint4*)(smu + PF_H2F);
#pragma unroll
        for (int ks = 0; ks < 8; ks++) {
            int base = ((ng * 8 + ks) * 32 + lane) * 2;
            uint4 b01 = w3u4[base];
            uint4 b23 = w3u4[base + 1];
#pragma unroll
            for (int im = 0; im < 3; im++)
                if (im < nmt) {
                    int mta = 2 * im + mg;
                    uint4 A = h2u4[(mta * 8 + ks) * 32 + lane];
                    mma16(acc3[im][0], A, b01.x, b01.y);
                    mma16(acc3[im][1], A, b01.z, b01.w);
                    mma16(acc3[im][2], A, b23.x, b23.y);
                    mma16(acc3[im][3], A, b23.z, b23.w);
                }
        }
        __syncthreads();  // B2 (H2F dead -> STG valid)

        // ---- stage + flush partial maxes to POOL; store next-tile NB ----
        {
            float* stg = sm + PF_STG + w * 528;
            float cur = NEGINF;
#pragma unroll
            for (int im = 0; im < 3; im++)
                if (im < nmt) {
                    __syncwarp();
#pragma unroll
                    for (int nq = 0; nq < 4; nq++)
#pragma unroll
                        for (int e = 0; e < 4; e++) {
                            int mr = (lane >> 2) + ((e >> 1) << 3);
                            int nc = nq * 8 + ((lane & 3) << 1) + (e & 1);
                            stg[mr * 33 + nc] = acc3[im][nq][e];
                        }
                    __syncwarp();
                    int mta = 2 * im + mg;
#pragma unroll
                    for (int r = 0; r < 16; r++) {
                        cur = fmaxf(cur, stg[r * 33 + lane]);
                        int grow = mta * 16 + r;
                        if (((grow + 1) % S) == 0 || r == 15) {
                            sm[PF_POOL + mg * 4096 + (grow / S) * 256 + ng * 32 + lane] = cur;
                            cur = NEGINF;
                        }
                    }
                }
        }
        if (pf) {
            sm[PF_NB + t * 4 + 0] = d0;
            sm[PF_NB + t * 4 + 1] = d1;
            sm[PF_NB + t * 4 + 2] = d2;
        }
        __syncthreads();  // B3

        // ---- combine + reset POOL + write feats ----
#pragma unroll
        for (int ii = 0; ii < PTS / 2; ii++) {
            int idx = t + ii * 512;
            int pt = idx >> 8, d = idx & 255;
            float v = fmaxf(sm[PF_POOL + idx], sm[PF_POOL + 4096 + idx]) + sm[PF_B3 + d];
            sm[PF_POOL + idx] = NEGINF;
            sm[PF_POOL + 4096 + idx] = NEGINF;
            g_feats[(size_t)(pt0 + pt) * 768 + SI * 256 + d] = v;
        }
        // ---- L1 for next tile ----
        if (tile + nblk < NT) {
#pragma unroll
            for (int ii = 0; ii < 5; ii++) {
                int i = t + ii * 512;
                int dd2 = i & 31, r = i >> 5, d = dd2 * 2;
                float v0 = sm[PF_B1 + d] + sm[PF_NB + r * 4] * sm[PF_W1 + d] +
                           sm[PF_NB + r * 4 + 1] * sm[PF_W1 + 64 + d] +
                           sm[PF_NB + r * 4 + 2] * sm[PF_W1 + 128 + d];
                float v1 = sm[PF_B1 + d + 1] + sm[PF_NB + r * 4] * sm[PF_W1 + d + 1] +
                           sm[PF_NB + r * 4 + 1] * sm[PF_W1 + 64 + d + 1] +
                           sm[PF_NB + r * 4 + 2] * sm[PF_W1 + 128 + d + 1];
                smu[PF_H1F + ((r >> 4) * 4 + (dd2 >> 3)) * 128 + ((r & 7) * 4 + (dd2 & 3)) * 4 +
                    (((r & 8) >> 3) | ((dd2 & 4) >> 1))] = packbf(lrelu(v0), lrelu(v1));
            }
        }
        __syncthreads();  // B4
    }
}

__global__ void __launch_bounds__(512) patch_all_kernel(
    const float* __restrict__ points, const void* __restrict__ nbr,
    const float* __restrict__ pb1, const float* __restrict__ pb2,
    const float* __restrict__ pb3) {
    extern __shared__ float sm[];
    int b = blockIdx.x;  // 296 blocks: 42 / 85 / 169 (~rows ratio 1:2:4)
    if (b < 42)       patch_run<0>(sm, b,       42,  points, nbr, pb1, pb2, pb3);
    else if (b < 127) patch_run<1>(sm, b - 42,  85,  points, nbr, pb1, pb2, pb3);
    else              patch_run<2>(sm, b - 127, 169, points, nbr, pb1, pb2, pb3);
}

// ======================= shared MLP: tf32 mma (proven R5 version) ======================
#define MF_A   0
#define MF_H1F 8192
#define MF_H3  8192
#define MF_H4  12352
#define MF_SB1 24576
#define MF_SB2 24832
#define MF_SB3 24960
#define MF_SB4 25024
#define MF_W5  25056
#define MF_W4  25088
#define MF_TOT 27136
#define SMEM_MLP (MF_TOT * 4)

__global__ void __launch_bounds__(256, 2) mlp_kernel(
    const float* __restrict__ sb1, const float* __restrict__ sb2,
    const float* __restrict__ sb3, const float* __restrict__ sb4,
    const float* __restrict__ sw5, const float* __restrict__ sb5,
    float* __restrict__ out) {
    extern __shared__ float sm[];
    const int t = threadIdx.x;
    const int w = t >> 5, lane = t & 31;
    const int pt0 = blockIdx.x * 64;

    for (int i = t; i < 2048; i += 256) sm[MF_W4 + i] = g_sw4T[i];
    if (t < 256) sm[MF_SB1 + t] = sb1[t];
    if (t < 128) sm[MF_SB2 + t] = sb2[t];
    if (t < 64) sm[MF_SB3 + t] = sb3[t];
    if (t < 32) {
        sm[MF_SB4 + t] = sb4[t];
        sm[MF_W5 + t] = sw5[t];
    }
    __syncthreads();

    float acc1[4][4][4];
#pragma unroll
    for (int mt = 0; mt < 4; mt++)
#pragma unroll
        for (int nt = 0; nt < 4; nt++)
#pragma unroll
            for (int e = 0; e < 4; e++) acc1[mt][nt][e] = 0.f;

    for (int c = 0; c < 6; c++) {
#pragma unroll
        for (int ii = 0; ii < 32; ii++) {
            int i = ii * 256 + t;
            int k3 = i & 7, mb0 = (i >> 3) & 1, mb3 = (i >> 4) & 1, q = ((i >> 5) & 3) << 1;
            int fr = i >> 7, ks = fr & 15, mt = fr >> 4;
            int m = mt * 16 + q + mb0 + (mb3 << 3);
            int kk = (ks << 3) | k3;
            int p = pt0 + m;
            if (p >= NPTS) p = NPTS - 1;
            float v = to_tf32(g_feats[(size_t)p * 768 + c * 128 + kk]);
            sm[MF_A + (mt * 16 + ks) * 128 + (((m & 7) << 2) | (kk & 3)) * 4 +
               (((m & 8) >> 3) | ((kk & 4) >> 1))] = v;
        }
        __syncthreads();
#pragma unroll 4
        for (int ks = 0; ks < 16; ks++) {
            uint32_t b[4][2];
#pragma unroll
            for (int nt = 0; nt < 4; nt++) {
                float2 v = *(const float2*)(g_sw1f +
                                            (((w * 4 + nt) * 96 + c * 16 + ks) * 32 + lane) * 2);
                b[nt][0] = __float_as_uint(v.x);
                b[nt][1] = __float_as_uint(v.y);
            }
#pragma unroll
            for (int mt = 0; mt < 4; mt++) {
                uint4 A = *(const uint4*)(sm + MF_A + (mt * 16 + ks) * 128 + lane * 4);
#pragma unroll
                for (int nt = 0; nt < 4; nt++) mma8(acc1[mt][nt], A, b[nt][0], b[nt][1]);
            }
        }
        __syncthreads();
    }
#pragma unroll
    for (int mt = 0; mt < 4; mt++)
#pragma unroll
        for (int nt = 0; nt < 4; nt++)
#pragma unroll
            for (int e = 0; e < 4; e++) {
                int m = mt * 16 + (lane >> 2) + ((e >> 1) << 3);
                int n = (w * 4 + nt) * 8 + ((lane & 3) << 1) + (e & 1);
                float v = to_tf32(lrelu(acc1[mt][nt][e] + sm[MF_SB1 + n]));
                sm[MF_H1F + (mt * 32 + (n >> 3)) * 128 + (((m & 7) << 2) | (n & 3)) * 4 +
                   (((m & 8) >> 3) | ((n & 4) >> 1))] = v;
            }
    __syncthreads();

    float acc2[4][2][4];
#pragma unroll
    for (int mt = 0; mt < 4; mt++)
#pragma unroll
        for (int j = 0; j < 2; j++)
#pragma unroll
            for (int e = 0; e < 4; e++) acc2[mt][j][e] = 0.f;
#pragma unroll 4
    for (int ks = 0; ks < 32; ks++) {
        uint32_t b[2][2];
#pragma unroll
        for (int j = 0; j < 2; j++) {
            float2 v = *(const float2*)(g_sw2f + (((w + j * 8) * 32 + ks) * 32 + lane) * 2);
            b[j][0] = __float_as_uint(v.x);
            b[j][1] = __float_as_uint(v.y);
        }
#pragma unroll
        for (int mt = 0; mt < 4; mt++) {
            uint4 A = *(const uint4*)(sm + MF_H1F + (mt * 32 + ks) * 128 + lane * 4);
            mma8(acc2[mt][0], A, b[0][0], b[0][1]);
            mma8(acc2[mt][1], A, b[1][0], b[1][1]);
        }
    }
#pragma unroll
    for (int mt = 0; mt < 4; mt++)
#pragma unroll
        for (int j = 0; j < 2; j++)
#pragma unroll
            for (int e = 0; e < 4; e++) {
                int m = mt * 16 + (lane >> 2) + ((e >> 1) << 3);
                int n = (w + j * 8) * 8 + ((lane & 3) << 1) + (e & 1);
                float v = to_tf32(lrelu(acc2[mt][j][e] + sm[MF_SB2 + n]));
                sm[MF_A + (mt * 16 + (n >> 3)) * 128 + (((m & 7) << 2) | (n & 3)) * 4 +
                   (((m & 8) >> 3) | ((n & 4) >> 1))] = v;
            }
    __syncthreads();

    float acc3[4][4];
#pragma unroll
    for (int mt = 0; mt < 4; mt++)
#pragma unroll
        for (int e = 0; e < 4; e++) acc3[mt][e] = 0.f;
#pragma unroll 4
    for (int ks = 0; ks < 16; ks++) {
        float2 v = *(const float2*)(g_sw3f + ((w * 16 + ks) * 32 + lane) * 2);
        uint32_t b0 = __float_as_uint(v.x), b1 = __float_as_uint(v.y);
#pragma unroll
        for (int mt = 0; mt < 4; mt++) {
            uint4 A = *(const uint4*)(sm + MF_A + (mt * 16 + ks) * 128 + lane * 4);
            mma8(acc3[mt], A, b0, b1);
        }
    }
#pragma unroll
    for (int mt = 0; mt < 4; mt++)
#pragma unroll
        for (int e = 0; e < 4; e++) {
            int m = mt * 16 + (lane >> 2) + ((e >> 1) << 3);
            int n = w * 8 + ((lane & 3) << 1) + (e & 1);
            sm[MF_H3 + m * 65 + n] = lrelu(acc3[mt][e] + sm[MF_SB3 + n]);
        }
    __syncthreads();

#pragma unroll
    for (int ii = 0; ii < 8; ii++) {
        int idx = t + ii * 256;
        int m = idx >> 5, d = idx & 31;
        float a = sm[MF_SB4 + d];
#pragma unroll 8
        for (int k = 0; k < 64; k++) a += sm[MF_H3 + m * 65 + k] * sm[MF_W4 + k * 32 + d];
        sm[MF_H4 + m * 33 + d] = lrelu(a);
    }
    __syncthreads();

    if (t < 64) {
        float s = __ldg(sb5);
#pragma unroll
        for (int k = 0; k < 32; k++) s += sm[MF_H4 + t * 33 + k] * sm[MF_W5 + k];
        int p = pt0 + t;
        if (p < NPTS) out[p] = s;
    }
}

// ======================= launch ========================================================
extern "C" void kernel_launch(void* const* d_in, const int* in_sizes, int n_in,
                              void* d_out, int out_size) {
    (void)out_size;
    const int want[18] = {300000, 2000000, 576, 192, 24576, 384, 98304, 768,
                          196608, 256,    32768, 128, 8192, 64,  2048,  32, 32, 1};
    const void* ptr[18] = {};
    {
        int used[64] = {};
        for (int w = 0; w < 18; w++) {
            for (int i = 0; i < n_in && i < 64; i++) {
                if (!used[i] && in_sizes[i] == want[w]) {
                    ptr[w] = d_in[i];
                    used[i] = 1;
                    break;
                }
            }
        }
        for (int w = 0; w < 18; w++)
            if (!ptr[w] && w < n_in) ptr[w] = d_in[w];
    }

    const float* points = (const float*)ptr[0];
    const void*  nbr    = ptr[1];
    const float* pw1 = (const float*)ptr[2];
    const float* pb1 = (const float*)ptr[3];
    const float* pw2 = (const float*)ptr[4];
    const float* pb2 = (const float*)ptr[5];
    const float* pw3 = (const float*)ptr[6];
    const float* pb3 = (const float*)ptr[7];
    const float* sw1 = (const float*)ptr[8];
    const float* sb1 = (const float*)ptr[9];
    const float* sw2 = (const float*)ptr[10];
    const float* sb2 = (const float*)ptr[11];
    const float* sw3 = (const float*)ptr[12];
    const float* sb3 = (const float*)ptr[13];
    const float* sw4 = (const float*)ptr[14];
    const float* sb4 = (const float*)ptr[15];
    const float* sw5 = (const float*)ptr[16];
    const float* sb5 = (const float*)ptr[17];

    cudaFuncSetAttribute(patch_all_kernel, cudaFuncAttributeMaxDynamicSharedMemorySize,
                         SMEM_PATCH);
    cudaFuncSetAttribute(mlp_kernel, cudaFuncAttributeMaxDynamicSharedMemorySize, SMEM_MLP);

    detect_kernel<<<1, 256>>>((const unsigned int*)nbr);
    prep_kernel<<<128, 256>>>(pw1, pw2, pw3, sw1, sw2, sw3, sw4);
    patch_all_kernel<<<296, 512, SMEM_PATCH>>>(points, nbr, pb1, pb2, pb3);
    mlp_kernel<<<(NPTS + 63) / 64, 256, SMEM_MLP>>>(sb1, sb2, sb3, sb4, sw5, sb5,
                                                    (float*)d_out);
}

// round 9
// speedup vs baseline: 2.2788x; 1.1822x over previous
#include <cuda_runtime.h>
#include <cstddef>
#include <cstdint>

#define NPTS 100000
#define KNN 20
#define NEGINF -3.4e38f

__device__ __forceinline__ float lrelu(float x) { return fmaxf(x, 0.2f * x); }
__device__ __forceinline__ uint32_t packbf(float lo, float hi) {
    uint32_t r;
    asm("cvt.rn.bf16x2.f32 %0, %1, %2;" : "=r"(r) : "f"(hi), "f"(lo));
    return r;
}
__device__ __forceinline__ void mma16(float* d, const uint4& a, uint32_t b0, uint32_t b1) {
    asm volatile(
        "mma.sync.aligned.m16n8k16.row.col.f32.bf16.bf16.f32 "
        "{%0,%1,%2,%3}, {%4,%5,%6,%7}, {%8,%9}, {%0,%1,%2,%3};"
        : "+f"(d[0]), "+f"(d[1]), "+f"(d[2]), "+f"(d[3])
        : "r"(a.x), "r"(a.y), "r"(a.z), "r"(a.w), "r"(b0), "r"(b1));
}
#define BAR_MG(id) asm volatile("bar.sync %0, 256;" ::"r"(id) : "memory")

// ======================= device scratch ================================================
__device__ int      g_idx64;
__device__ float    g_w1T[3 * 3 * 64];
__device__ uint32_t g_w2b[3 * 4096];    // patch W2 bf16 B-frags
__device__ uint32_t g_w3b[3 * 16384];   // patch W3 bf16 B-frags, pair-major (LDS.128 CF)
__device__ uint32_t g_sw1b[32 * 48 * 64];  // MLP W1 bf16 B-frags
__device__ uint32_t g_sw2b[16 * 16 * 64];
__device__ uint32_t g_sw3b[8 * 8 * 64];
__device__ float    g_sw4T[64 * 32];
__device__ float    g_feats[(size_t)NPTS * 768];

__global__ void detect_kernel(const unsigned int* __restrict__ raw) {
    __shared__ int flag;
    if (threadIdx.x == 0) flag = 0;
    __syncthreads();
    if (raw[2 * threadIdx.x + 1] != 0u) atomicOr(&flag, 1);
    __syncthreads();
    if (threadIdx.x == 0) g_idx64 = (flag == 0) ? 1 : 0;
}

__global__ void prep_kernel(const float* __restrict__ pw1, const float* __restrict__ pw2,
                            const float* __restrict__ pw3, const float* __restrict__ sw1,
                            const float* __restrict__ sw2, const float* __restrict__ sw3,
                            const float* __restrict__ sw4) {
    const int tid = blockIdx.x * blockDim.x + threadIdx.x;
    const int stride = gridDim.x * blockDim.x;
    for (int i = tid; i < 3 * 3 * 64; i += stride) {
        int s = i / 192, r = i % 192, c = r / 64, d = r % 64;
        g_w1T[i] = pw1[s * 192 + d * 3 + c];
    }
    // patch W2 bf16 B-frags (k16): [nt(16)][ks(4)][lane][reg(2)]
    for (int i = tid; i < 3 * 128 * 32; i += stride) {
        int s = i / 4096, r = i % 4096, n = r >> 5, k2 = r & 31, k = k2 * 2;
        float v0 = pw2[s * 8192 + n * 64 + k];
        float v1 = pw2[s * 8192 + n * 64 + k + 1];
        int idx = (((n >> 3) * 4 + (k2 >> 3)) * 32 + (n & 7) * 4 + (k2 & 3)) * 2 +
                  ((k2 >> 2) & 1);
        g_w2b[s * 4096 + idx] = packbf(v0, v1);
    }
    // patch W3 bf16 B-frags, pair-major: [ng(8)][ks(8)][pair(2)][lane(32)][nqi(2)][reg(2)]
    for (int i = tid; i < 3 * 256 * 64; i += stride) {
        int s = i >> 14, r = i & 16383, n = r >> 6, k2 = r & 63, k = k2 * 2;
        float v0 = pw3[s * 32768 + n * 128 + k];
        float v1 = pw3[s * 32768 + n * 128 + k + 1];
        int ng = n >> 5, nq = (n >> 3) & 3, pair = nq >> 1, nqi = nq & 1;
        int ks = k2 >> 3, reg = (k2 >> 2) & 1, lane = (n & 7) * 4 + (k2 & 3);
        int idx = ((((ng * 8 + ks) * 2 + pair) * 32 + lane) * 4) + nqi * 2 + reg;
        g_w3b[s * 16384 + idx] = packbf(v0, v1);
    }
    // MLP bf16 B-frags: [nt][ks][lane][reg]
    for (int i = tid; i < 256 * 384; i += stride) {
        int n = i / 384, kp = i % 384;
        int ks = kp >> 3, k2 = kp & 7;
        int idx = ((n >> 3) * 48 + ks) * 64 + ((n & 7) * 4 + (k2 & 3)) * 2 + ((k2 >> 2) & 1);
        g_sw1b[idx] = packbf(sw1[n * 768 + 2 * kp], sw1[n * 768 + 2 * kp + 1]);
    }
    for (int i = tid; i < 128 * 128; i += stride) {
        int n = i >> 7, kp = i & 127;
        int ks = kp >> 3, k2 = kp & 7;
        int idx = ((n >> 3) * 16 + ks) * 64 + ((n & 7) * 4 + (k2 & 3)) * 2 + ((k2 >> 2) & 1);
        g_sw2b[idx] = packbf(sw2[n * 256 + 2 * kp], sw2[n * 256 + 2 * kp + 1]);
    }
    for (int i = tid; i < 64 * 64; i += stride) {
        int n = i >> 6, kp = i & 63;
        int ks = kp >> 3, k2 = kp & 7;
        int idx = ((n >> 3) * 8 + ks) * 64 + ((n & 7) * 4 + (k2 & 3)) * 2 + ((k2 >> 2) & 1);
        g_sw3b[idx] = packbf(sw3[n * 128 + 2 * kp], sw3[n * 128 + 2 * kp + 1]);
    }
    for (int i = tid; i < 64 * 32; i += stride) {
        int k = i >> 5, d = i & 31;
        g_sw4T[i] = sw4[d * 64 + k];
    }
}

// ======================= patch stage: bf16, pipelined, lean barriers ===================
// word offsets (4B units)
#define PF_W3F  0        // 16384
#define PF_H2F  16384    // 5120
#define PF_STG  21504    // 16*528 = 8448 (dedicated; no alias)
#define PF_POOL 29952    // 2*4096
#define PF_H1F  38144    // 2560
#define PF_NB   40704    // 320
#define PF_W1   41024
#define PF_B1   41216
#define PF_B2   41280
#define PF_B3   41408
#define PF_TOT  41664
#define SMEM_PATCH (PF_TOT * 4)

template <int SI>
__device__ __forceinline__ void patch_run(
    float* sm, int bid, int nblk,
    const float* __restrict__ points, const void* __restrict__ nbr,
    const float* __restrict__ pb1, const float* __restrict__ pb2,
    const float* __restrict__ pb3) {
    constexpr int S = (SI == 0) ? 5 : (SI == 1 ? 10 : 20);
    constexpr int PTS = 80 / S;
    constexpr int NT = NPTS / PTS;

    uint32_t* smu = (uint32_t*)sm;
    const int t = threadIdx.x;
    const int w = t >> 5, lane = t & 31;
    const int ng = w & 7, mg = w >> 3;
    const int nmt = mg ? 2 : 3;
    const int is64 = g_idx64;

    {
        const uint4* src = (const uint4*)g_w3b + SI * 4096;
        uint4* dst = (uint4*)(smu + PF_W3F);
        for (int i = t; i < 4096; i += 512) dst[i] = src[i];
        for (int i = t; i < 192; i += 512) sm[PF_W1 + i] = g_w1T[SI * 192 + i];
        if (t < 64) sm[PF_B1 + t] = pb1[SI * 64 + t];
        if (t < 128) sm[PF_B2 + t] = pb2[SI * 128 + t];
        if (t < 256) sm[PF_B3 + t] = pb3[SI * 256 + t];
#pragma unroll
        for (int ii = 0; ii < 16; ii++) sm[PF_POOL + t + ii * 512] = NEGINF;
    }
    uint32_t bw2[2][4][2];
#pragma unroll
    for (int nl = 0; nl < 2; nl++)
#pragma unroll
        for (int ks = 0; ks < 4; ks++) {
            uint2 v = *(const uint2*)(g_w2b + SI * 4096 +
                                      (((2 * ng + nl) * 4 + ks) * 32 + lane) * 2);
            bw2[nl][ks][0] = v.x;
            bw2[nl][ks][1] = v.y;
        }
    float b2e[2], b2o[2];
#pragma unroll
    for (int nl = 0; nl < 2; nl++) {
        int n0 = ng * 16 + nl * 8 + (lane & 3) * 2;
        b2e[nl] = pb2[SI * 128 + n0];
        b2o[nl] = pb2[SI * 128 + n0 + 1];
    }
    if (t < 80) {
        const int p = bid * PTS + t / S, j = t % S;
        long long gi = is64 ? ((const long long*)nbr)[(size_t)p * KNN + j]
                            : (long long)((const int*)nbr)[p * KNN + j];
        const float* q = points + gi * 3;
        const float* c = points + (long long)p * 3;
        sm[PF_NB + t * 4 + 0] = q[0] - c[0];
        sm[PF_NB + t * 4 + 1] = q[1] - c[1];
        sm[PF_NB + t * 4 + 2] = q[2] - c[2];
    }
    __syncthreads();
#pragma unroll
    for (int ii = 0; ii < 5; ii++) {
        int i = t + ii * 512;
        int d2 = i & 31, r = i >> 5, d = d2 * 2;
        float v0 = sm[PF_B1 + d] + sm[PF_NB + r * 4] * sm[PF_W1 + d] +
                   sm[PF_NB + r * 4 + 1] * sm[PF_W1 + 64 + d] +
                   sm[PF_NB + r * 4 + 2] * sm[PF_W1 + 128 + d];
        float v1 = sm[PF_B1 + d + 1] + sm[PF_NB + r * 4] * sm[PF_W1 + d + 1] +
                   sm[PF_NB + r * 4 + 1] * sm[PF_W1 + 64 + d + 1] +
                   sm[PF_NB + r * 4 + 2] * sm[PF_W1 + 128 + d + 1];
        smu[PF_H1F + ((r >> 4) * 4 + (d2 >> 3)) * 128 + ((r & 7) * 4 + (d2 & 3)) * 4 +
            (((r & 8) >> 3) | ((d2 & 4) >> 1))] = packbf(lrelu(v0), lrelu(v1));
    }
    __syncthreads();

    for (int tile = bid; tile < NT; tile += nblk) {
        const int pt0 = tile * PTS;
        const bool pf = (t < 80) && (tile + nblk < NT);

        long long gi_n = 0;
        int pn = 0;
        if (pf) {
            pn = (tile + nblk) * PTS + t / S;
            int j = t % S;
            gi_n = is64 ? ((const long long*)nbr)[(size_t)pn * KNN + j]
                        : (long long)((const int*)nbr)[pn * KNN + j];
        }

        // ---- L2 mma ----
        float acc2[3][2][4];
#pragma unroll
        for (int im = 0; im < 3; im++)
#pragma unroll
            for (int nl = 0; nl < 2; nl++)
#pragma unroll
                for (int e = 0; e < 4; e++) acc2[im][nl][e] = 0.f;
        const uint4* h1u4 = (const uint4*)(smu + PF_H1F);
#pragma unroll
        for (int ks = 0; ks < 4; ks++)
#pragma unroll
            for (int im = 0; im < 3; im++)
                if (im < nmt) {
                    int mta = 2 * im + mg;
                    uint4 A = h1u4[(mta * 4 + ks) * 32 + lane];
                    mma16(acc2[im][0], A, bw2[0][ks][0], bw2[0][ks][1]);
                    mma16(acc2[im][1], A, bw2[1][ks][0], bw2[1][ks][1]);
                }
        // ---- L2 epilogue -> H2F ----
        {
            uint4* h2u4 = (uint4*)(smu + PF_H2F);
#pragma unroll
            for (int im = 0; im < 3; im++)
                if (im < nmt) {
                    int mta = 2 * im + mg;
                    uint4 v;
                    v.x = packbf(lrelu(acc2[im][0][0] + b2e[0]), lrelu(acc2[im][0][1] + b2o[0]));
                    v.y = packbf(lrelu(acc2[im][0][2] + b2e[0]), lrelu(acc2[im][0][3] + b2o[0]));
                    v.z = packbf(lrelu(acc2[im][1][0] + b2e[1]), lrelu(acc2[im][1][1] + b2o[1]));
                    v.w = packbf(lrelu(acc2[im][1][2] + b2e[1]), lrelu(acc2[im][1][3] + b2o[1]));
                    h2u4[(mta * 8 + ng) * 32 + lane] = v;
                }
        }
        BAR_MG(1 + mg);  // per-parity barrier (H2F parity slices disjoint)

        float d0 = 0.f, d1 = 0.f, d2 = 0.f;
        if (pf) {
            const float* q = points + gi_n * 3;
            const float* c = points + (long long)pn * 3;
            d0 = q[0] - c[0];
            d1 = q[1] - c[1];
            d2 = q[2] - c[2];
        }

        // ---- L3 mma (conflict-free B reads) ----
        float acc3[3][4][4];
#pragma unroll
        for (int im = 0; im < 3; im++)
#pragma unroll
            for (int nq = 0; nq < 4; nq++)
#pragma unroll
                for (int e = 0; e < 4; e++) acc3[im][nq][e] = 0.f;
        const uint4* w3u4 = (const uint4*)(smu + PF_W3F);
        const uint4* h2u4 = (const uint4*)(smu + PF_H2F);
#pragma unroll
        for (int ks = 0; ks < 8; ks++) {
            int base = ((ng * 8 + ks) * 2) * 32 + lane;
            uint4 b01 = w3u4[base];
            uint4 b23 = w3u4[base + 32];
#pragma unroll
            for (int im = 0; im < 3; im++)
                if (im < nmt) {
                    int mta = 2 * im + mg;
                    uint4 A = h2u4[(mta * 8 + ks) * 32 + lane];
                    mma16(acc3[im][0], A, b01.x, b01.y);
                    mma16(acc3[im][1], A, b01.z, b01.w);
                    mma16(acc3[im][2], A, b23.x, b23.y);
                    mma16(acc3[im][3], A, b23.z, b23.w);
                }
        }
        // (former B2 deleted: STG is dedicated + warp-private; POOL is parity-private)

        // ---- stage + flush partial maxes; store next-tile NB ----
        {
            float* stg = sm + PF_STG + w * 528;
            float cur = NEGINF;
#pragma unroll
            for (int im = 0; im < 3; im++)
                if (im < nmt) {
                    __syncwarp();
#pragma unroll
                    for (int nq = 0; nq < 4; nq++)
#pragma unroll
                        for (int e = 0; e < 4; e++) {
                            int mr = (lane >> 2) + ((e >> 1) << 3);
                            int nc = nq * 8 + ((lane & 3) << 1) + (e & 1);
                            stg[mr * 33 + nc] = acc3[im][nq][e];
                        }
                    __syncwarp();
                    int mta = 2 * im + mg;
#pragma unroll
                    for (int r = 0; r < 16; r++) {
                        cur = fmaxf(cur, stg[r * 33 + lane]);
                        int grow = mta * 16 + r;
                        if (((grow + 1) % S) == 0 || r == 15) {
                            sm[PF_POOL + mg * 4096 + (grow / S) * 256 + ng * 32 + lane] = cur;
                            cur = NEGINF;
                        }
                    }
                }
        }
        if (pf) {
            sm[PF_NB + t * 4 + 0] = d0;
            sm[PF_NB + t * 4 + 1] = d1;
            sm[PF_NB + t * 4 + 2] = d2;
        }
        __syncthreads();  // B3

        // ---- combine + reset POOL + write feats ----
#pragma unroll
        for (int ii = 0; ii < PTS / 2; ii++) {
            int idx = t + ii * 512;
            int pt = idx >> 8, d = idx & 255;
            float v = fmaxf(sm[PF_POOL + idx], sm[PF_POOL + 4096 + idx]) + sm[PF_B3 + d];
            sm[PF_POOL + idx] = NEGINF;
            sm[PF_POOL + 4096 + idx] = NEGINF;
            g_feats[(size_t)(pt0 + pt) * 768 + SI * 256 + d] = v;
        }
        // ---- L1 for next tile ----
        if (tile + nblk < NT) {
#pragma unroll
            for (int ii = 0; ii < 5; ii++) {
                int i = t + ii * 512;
                int dd2 = i & 31, r = i >> 5, d = dd2 * 2;
                float v0 = sm[PF_B1 + d] + sm[PF_NB + r * 4] * sm[PF_W1 + d] +
                           sm[PF_NB + r * 4 + 1] * sm[PF_W1 + 64 + d] +
                           sm[PF_NB + r * 4 + 2] * sm[PF_W1 + 128 + d];
                float v1 = sm[PF_B1 + d + 1] + sm[PF_NB + r * 4] * sm[PF_W1 + d + 1] +
                           sm[PF_NB + r * 4 + 1] * sm[PF_W1 + 64 + d + 1] +
                           sm[PF_NB + r * 4 + 2] * sm[PF_W1 + 128 + d + 1];
                smu[PF_H1F + ((r >> 4) * 4 + (dd2 >> 3)) * 128 + ((r & 7) * 4 + (dd2 & 3)) * 4 +
                    (((r & 8) >> 3) | ((dd2 & 4) >> 1))] = packbf(lrelu(v0), lrelu(v1));
            }
        }
        __syncthreads();  // B4
    }
}

__global__ void __launch_bounds__(512) patch_all_kernel(
    const float* __restrict__ points, const void* __restrict__ nbr,
    const float* __restrict__ pb1, const float* __restrict__ pb2,
    const float* __restrict__ pb3) {
    extern __shared__ float sm[];
    int b = blockIdx.x;
    if (b < 42)       patch_run<0>(sm, b,       42,  points, nbr, pb1, pb2, pb3);
    else if (b < 127) patch_run<1>(sm, b - 42,  85,  points, nbr, pb1, pb2, pb3);
    else              patch_run<2>(sm, b - 127, 169, points, nbr, pb1, pb2, pb3);
}

// ======================= shared MLP: bf16 mma ==========================================
// word offsets
#define MF_A   0        // 4096 u32 (A chunk / L3 A-frags)
#define MF_H1F 4096     // 8192 u32 ; after L2: H3 (64*65) at 4096, H4 at 8256
#define MF_H3  4096
#define MF_H4  8256
#define MF_SB1 12288
#define MF_SB2 12544
#define MF_SB3 12672
#define MF_SB4 12736
#define MF_W5  12768
#define MF_W4  12800    // 2048
#define MF_TOT 14848
#define SMEM_MLP (MF_TOT * 4)

__global__ void __launch_bounds__(256, 2) mlp_kernel(
    const float* __restrict__ sb1, const float* __restrict__ sb2,
    const float* __restrict__ sb3, const float* __restrict__ sb4,
    const float* __restrict__ sw5, const float* __restrict__ sb5,
    float* __restrict__ out) {
    extern __shared__ float sm[];
    uint32_t* smu = (uint32_t*)sm;
    const int t = threadIdx.x;
    const int w = t >> 5, lane = t & 31;
    const int pt0 = blockIdx.x * 64;

    for (int i = t; i < 2048; i += 256) sm[MF_W4 + i] = g_sw4T[i];
    if (t < 256) sm[MF_SB1 + t] = sb1[t];
    if (t < 128) sm[MF_SB2 + t] = sb2[t];
    if (t < 64) sm[MF_SB3 + t] = sb3[t];
    if (t < 32) {
        sm[MF_SB4 + t] = sb4[t];
        sm[MF_W5 + t] = sw5[t];
    }
    __syncthreads();

    // ---- L1: 768 -> 256 bf16, 6 chunks of 8 k16-steps ----
    float acc1[4][4][4];
#pragma unroll
    for (int mt = 0; mt < 4; mt++)
#pragma unroll
        for (int nt = 0; nt < 4; nt++)
#pragma unroll
            for (int e = 0; e < 4; e++) acc1[mt][nt][e] = 0.f;

    for (int c = 0; c < 6; c++) {
        // gmem -> bf16 A-frags (dst index == i: conflict-free)
#pragma unroll
        for (int ii = 0; ii < 16; ii++) {
            int i = ii * 256 + t;
            int reg = i & 3, ln = (i >> 2) & 31, ksl = (i >> 7) & 7, mt = i >> 10;
            int row = (ln >> 2) + 8 * (reg & 1);
            int kpair = ksl * 8 + (ln & 3) + 4 * (reg >> 1);
            int p = pt0 + mt * 16 + row;
            if (p >= NPTS) p = NPTS - 1;
            float2 f = *(const float2*)(g_feats + (size_t)p * 768 + c * 128 + kpair * 2);
            smu[MF_A + i] = packbf(f.x, f.y);
        }
        __syncthreads();
        const uint2* w1b = (const uint2*)g_sw1b;
        const uint4* au4 = (const uint4*)(smu + MF_A);
#pragma unroll
        for (int ksl = 0; ksl < 8; ksl++) {
            uint2 b[4];
#pragma unroll
            for (int nt = 0; nt < 4; nt++)
                b[nt] = w1b[((w * 4 + nt) * 48 + c * 8 + ksl) * 32 + lane];
#pragma unroll
            for (int mt = 0; mt < 4; mt++) {
                uint4 A = au4[(mt * 8 + ksl) * 32 + lane];
#pragma unroll
                for (int nt = 0; nt < 4; nt++) mma16(acc1[mt][nt], A, b[nt].x, b[nt].y);
            }
        }
        __syncthreads();
    }
    // L1 epilogue -> H1F bf16 A-frags (k=256 -> 16 ks)
#pragma unroll
    for (int mt = 0; mt < 4; mt++)
#pragma unroll
        for (int nt = 0; nt < 4; nt++) {
            int n0 = (w * 4 + nt) * 8 + (lane & 3) * 2;
            float be = sm[MF_SB1 + n0], bo = sm[MF_SB1 + n0 + 1];
            uint32_t lo = packbf(lrelu(acc1[mt][nt][0] + be), lrelu(acc1[mt][nt][1] + bo));
            uint32_t hi = packbf(lrelu(acc1[mt][nt][2] + be), lrelu(acc1[mt][nt][3] + bo));
            int kp = (w * 4 + nt) * 4 + (lane & 3);
            int ks = kp >> 3, kpf = kp & 7;
            int lanep = (lane >> 2) * 4 + (kpf & 3);
            int r0 = (kpf & 4) >> 1;
            *(uint2*)(smu + MF_H1F + (mt * 16 + ks) * 128 + lanep * 4 + r0) =
                make_uint2(lo, hi);
        }
    __syncthreads();

    // ---- L2: 256 -> 128 bf16 (warp owns nt {w, w+8}) ----
    float acc2[4][2][4];
#pragma unroll
    for (int mt = 0; mt < 4; mt++)
#pragma unroll
        for (int j = 0; j < 2; j++)
#pragma unroll
            for (int e = 0; e < 4; e++) acc2[mt][j][e] = 0.f;
    {
        const uint2* w2b = (const uint2*)g_sw2b;
        const uint4* au4 = (const uint4*)(smu + MF_H1F);
#pragma unroll 4
        for (int ks = 0; ks < 16; ks++) {
            uint2 b0 = w2b[(w * 16 + ks) * 32 + lane];
            uint2 b1 = w2b[((w + 8) * 16 + ks) * 32 + lane];
#pragma unroll
            for (int mt = 0; mt < 4; mt++) {
                uint4 A = au4[(mt * 16 + ks) * 32 + lane];
                mma16(acc2[mt][0], A, b0.x, b0.y);
                mma16(acc2[mt][1], A, b1.x, b1.y);
            }
        }
    }
    __syncthreads();
    // L2 epilogue -> MF_A bf16 A-frags (k=128 -> 8 ks)
#pragma unroll
    for (int mt = 0; mt < 4; mt++)
#pragma unroll
        for (int j = 0; j < 2; j++) {
            int n0 = (w + j * 8) * 8 + (lane & 3) * 2;
            float be = sm[MF_SB2 + n0], bo = sm[MF_SB2 + n0 + 1];
            uint32_t lo = packbf(lrelu(acc2[mt][j][0] + be), lrelu(acc2[mt][j][1] + bo));
            uint32_t hi = packbf(lrelu(acc2[mt][j][2] + be), lrelu(acc2[mt][j][3] + bo));
            int kp = (w + j * 8) * 4 + (lane & 3);
            int ks = kp >> 3, kpf = kp & 7;
            int lanep = (lane >> 2) * 4 + (kpf & 3);
            int r0 = (kpf & 4) >> 1;
            *(uint2*)(smu + MF_A + (mt * 8 + ks) * 128 + lanep * 4 + r0) = make_uint2(lo, hi);
        }
    __syncthreads();

    // ---- L3: 128 -> 64 bf16 (warp owns nt w) ----
    float acc3[4][4];
#pragma unroll
    for (int mt = 0; mt < 4; mt++)
#pragma unroll
        for (int e = 0; e < 4; e++) acc3[mt][e] = 0.f;
    {
        const uint2* w3b = (const uint2*)g_sw3b;
        const uint4* au4 = (const uint4*)(smu + MF_A);
#pragma unroll
        for (int ks = 0; ks < 8; ks++) {
            uint2 b = w3b[(w * 8 + ks) * 32 + lane];
#pragma unroll
            for (int mt = 0; mt < 4; mt++) {
                uint4 A = au4[(mt * 8 + ks) * 32 + lane];
                mma16(acc3[mt], A, b.x, b.y);
            }
        }
    }
    __syncthreads();  // MF_H1F dead -> H3 region valid
#pragma unroll
    for (int mt = 0; mt < 4; mt++)
#pragma unroll
        for (int e = 0; e < 4; e++) {
            int m = mt * 16 + (lane >> 2) + ((e >> 1) << 3);
            int n = w * 8 + ((lane & 3) << 1) + (e & 1);
            sm[MF_H3 + m * 65 + n] = lrelu(acc3[mt][e] + sm[MF_SB3 + n]);
        }
    __syncthreads();

    // ---- L4 scalar: 64 -> 32 ----
#pragma unroll
    for (int ii = 0; ii < 8; ii++) {
        int idx = t + ii * 256;
        int m = idx >> 5, d = idx & 31;
        float a = sm[MF_SB4 + d];
#pragma unroll 8
        for (int k = 0; k < 64; k++) a += sm[MF_H3 + m * 65 + k] * sm[MF_W4 + k * 32 + d];
        sm[MF_H4 + m * 33 + d] = lrelu(a);
    }
    __syncthreads();

    // ---- L5: 32 -> 1 ----
    if (t < 64) {
        float s = __ldg(sb5);
#pragma unroll
        for (int k = 0; k < 32; k++) s += sm[MF_H4 + t * 33 + k] * sm[MF_W5 + k];
        int p = pt0 + t;
        if (p < NPTS) out[p] = s;
    }
}

// ======================= launch ========================================================
extern "C" void kernel_launch(void* const* d_in, const int* in_sizes, int n_in,
                              void* d_out, int out_size) {
    (void)out_size;
    const int want[18] = {300000, 2000000, 576, 192, 24576, 384, 98304, 768,
                          196608, 256,    32768, 128, 8192, 64,  2048,  32, 32, 1};
    const void* ptr[18] = {};
    {
        int used[64] = {};
        for (int w = 0; w < 18; w++) {
            for (int i = 0; i < n_in && i < 64; i++) {
                if (!used[i] && in_sizes[i] == want[w]) {
                    ptr[w] = d_in[i];
                    used[i] = 1;
                    break;
                }
            }
        }
        for (int w = 0; w < 18; w++)
            if (!ptr[w] && w < n_in) ptr[w] = d_in[w];
    }

    const float* points = (const float*)ptr[0];
    const void*  nbr    = ptr[1];
    const float* pw1 = (const float*)ptr[2];
    const float* pb1 = (const float*)ptr[3];
    const float* pw2 = (const float*)ptr[4];
    const float* pb2 = (const float*)ptr[5];
    const float* pw3 = (const float*)ptr[6];
    const float* pb3 = (const float*)ptr[7];
    const float* sw1 = (const float*)ptr[8];
    const float* sb1 = (const float*)ptr[9];
    const float* sw2 = (const float*)ptr[10];
    const float* sb2 = (const float*)ptr[11];
    const float* sw3 = (const float*)ptr[12];
    const float* sb3 = (const float*)ptr[13];
    const float* sw4 = (const float*)ptr[14];
    const float* sb4 = (const float*)ptr[15];
    const float* sw5 = (const float*)ptr[16];
    const float* sb5 = (const float*)ptr[17];

    cudaFuncSetAttribute(patch_all_kernel, cudaFuncAttributeMaxDynamicSharedMemorySize,
                         SMEM_PATCH);
    cudaFuncSetAttribute(mlp_kernel, cudaFuncAttributeMaxDynamicSharedMemorySize, SMEM_MLP);

    detect_kernel<<<1, 256>>>((const unsigned int*)nbr);
    prep_kernel<<<128, 256>>>(pw1, pw2, pw3, sw1, sw2, sw3, sw4);
    patch_all_kernel<<<296, 512, SMEM_PATCH>>>(points, nbr, pb1, pb2, pb3);
    mlp_kernel<<<(NPTS + 63) / 64, 256, SMEM_MLP>>>(sb1, sb2, sb3, sb4, sw5, sb5,
                                                    (float*)d_out);
}

// round 11
// speedup vs baseline: 2.8866x; 1.2667x over previous
#include <cuda_runtime.h>
#include <cstddef>
#include <cstdint>

#define NPTS 100000
#define KNN 20
#define NEGINF -3.4e38f

__device__ __forceinline__ float lrelu(float x) { return fmaxf(x, 0.2f * x); }
__device__ __forceinline__ uint32_t packbf(float lo, float hi) {
    uint32_t r;
    asm("cvt.rn.bf16x2.f32 %0, %1, %2;" : "=r"(r) : "f"(hi), "f"(lo));
    return r;
}
__device__ __forceinline__ void mma16(float* d, const uint4& a, uint32_t b0, uint32_t b1) {
    asm volatile(
        "mma.sync.aligned.m16n8k16.row.col.f32.bf16.bf16.f32 "
        "{%0,%1,%2,%3}, {%4,%5,%6,%7}, {%8,%9}, {%0,%1,%2,%3};"
        : "+f"(d[0]), "+f"(d[1]), "+f"(d[2]), "+f"(d[3])
        : "r"(a.x), "r"(a.y), "r"(a.z), "r"(a.w), "r"(b0), "r"(b1));
}
#define BAR_MG(id) asm volatile("bar.sync %0, 256;" ::"r"(id) : "memory")

// ======================= device scratch ================================================
__device__ int      g_idx64;
__device__ float    g_w1T[3 * 3 * 64];
__device__ uint32_t g_w2b[3 * 4096];       // patch W2 bf16 B-frags
__device__ uint32_t g_w3b[3 * 16384];      // patch W3 bf16 B-frags, pair-major
__device__ uint32_t g_sw1b[32 * 48 * 64];  // MLP bf16 B-frags
__device__ uint32_t g_sw2b[16 * 16 * 64];
__device__ uint32_t g_sw3b[8 * 8 * 64];
__device__ float    g_sw4T[64 * 32];
__device__ uint32_t g_featsb[(size_t)NPTS * 384];  // feats as bf16x2 pairs

__global__ void detect_kernel(const unsigned int* __restrict__ raw) {
    __shared__ int flag;
    if (threadIdx.x == 0) flag = 0;
    __syncthreads();
    if (raw[2 * threadIdx.x + 1] != 0u) atomicOr(&flag, 1);
    __syncthreads();
    if (threadIdx.x == 0) g_idx64 = (flag == 0) ? 1 : 0;
}

__global__ void prep_kernel(const float* __restrict__ pw1, const float* __restrict__ pw2,
                            const float* __restrict__ pw3, const float* __restrict__ sw1,
                            const float* __restrict__ sw2, const float* __restrict__ sw3,
                            const float* __restrict__ sw4) {
    const int tid = blockIdx.x * blockDim.x + threadIdx.x;
    const int stride = gridDim.x * blockDim.x;
    for (int i = tid; i < 3 * 3 * 64; i += stride) {
        int s = i / 192, r = i % 192, c = r / 64, d = r % 64;
        g_w1T[i] = pw1[s * 192 + d * 3 + c];
    }
    for (int i = tid; i < 3 * 128 * 32; i += stride) {
        int s = i / 4096, r = i % 4096, n = r >> 5, k2 = r & 31, k = k2 * 2;
        float v0 = pw2[s * 8192 + n * 64 + k];
        float v1 = pw2[s * 8192 + n * 64 + k + 1];
        int idx = (((n >> 3) * 4 + (k2 >> 3)) * 32 + (n & 7) * 4 + (k2 & 3)) * 2 +
                  ((k2 >> 2) & 1);
        g_w2b[s * 4096 + idx] = packbf(v0, v1);
    }
    for (int i = tid; i < 3 * 256 * 64; i += stride) {
        int s = i >> 14, r = i & 16383, n = r >> 6, k2 = r & 63, k = k2 * 2;
        float v0 = pw3[s * 32768 + n * 128 + k];
        float v1 = pw3[s * 32768 + n * 128 + k + 1];
        int ng = n >> 5, nq = (n >> 3) & 3, pair = nq >> 1, nqi = nq & 1;
        int ks = k2 >> 3, reg = (k2 >> 2) & 1, lane = (n & 7) * 4 + (k2 & 3);
        int idx = ((((ng * 8 + ks) * 2 + pair) * 32 + lane) * 4) + nqi * 2 + reg;
        g_w3b[s * 16384 + idx] = packbf(v0, v1);
    }
    for (int i = tid; i < 256 * 384; i += stride) {
        int n = i / 384, kp = i % 384;
        int ks = kp >> 3, k2 = kp & 7;
        int idx = ((n >> 3) * 48 + ks) * 64 + ((n & 7) * 4 + (k2 & 3)) * 2 + ((k2 >> 2) & 1);
        g_sw1b[idx] = packbf(sw1[n * 768 + 2 * kp], sw1[n * 768 + 2 * kp + 1]);
    }
    for (int i = tid; i < 128 * 128; i += stride) {
        int n = i >> 7, kp = i & 127;
        int ks = kp >> 3, k2 = kp & 7;
        int idx = ((n >> 3) * 16 + ks) * 64 + ((n & 7) * 4 + (k2 & 3)) * 2 + ((k2 >> 2) & 1);
        g_sw2b[idx] = packbf(sw2[n * 256 + 2 * kp], sw2[n * 256 + 2 * kp + 1]);
    }
    for (int i = tid; i < 64 * 64; i += stride) {
        int n = i >> 6, kp = i & 63;
        int ks = kp >> 3, k2 = kp & 7;
        int idx = ((n >> 3) * 8 + ks) * 64 + ((n & 7) * 4 + (k2 & 3)) * 2 + ((k2 >> 2) & 1);
        g_sw3b[idx] = packbf(sw3[n * 128 + 2 * kp], sw3[n * 128 + 2 * kp + 1]);
    }
    for (int i = tid; i < 64 * 32; i += stride) {
        int k = i >> 5, d = i & 31;
        g_sw4T[i] = sw4[d * 64 + k];
    }
}

// ======================= patch stage: 160-row supertile, bf16 ==========================
#define PF_W3F  0        // 16384
#define PF_H2F  16384    // 10240
#define PF_STG  26624    // 16*528
#define PF_H1F  35072    // 5120
#define PF_NB   40192    // 640
#define PF_W1   40832    // 192
#define PF_B1   41024    // 64
#define PF_TOT  41088
#define SMEM_PATCH (PF_TOT * 4)
#define TROWS 160

template <int SI>
__device__ __forceinline__ void patch_run(
    float* sm, int bid, int nblk,
    const float* __restrict__ points, const void* __restrict__ nbr,
    const float* __restrict__ pb1, const float* __restrict__ pb2,
    const float* __restrict__ pb3) {
    constexpr int S = (SI == 0) ? 5 : (SI == 1 ? 10 : 20);
    constexpr int PTS = TROWS / S;
    constexpr int NT = NPTS / PTS;

    uint32_t* smu = (uint32_t*)sm;
    const int t = threadIdx.x;
    const int w = t >> 5, lane = t & 31;
    const int ng = w & 7, mg = w >> 3;   // mg: mt half {0..4} / {5..9}
    const int is64 = g_idx64;

    {
        const uint4* src = (const uint4*)g_w3b + SI * 4096;
        uint4* dst = (uint4*)(smu + PF_W3F);
        for (int i = t; i < 4096; i += 512) dst[i] = src[i];
        for (int i = t; i < 192; i += 512) sm[PF_W1 + i] = g_w1T[SI * 192 + i];
        if (t < 64) sm[PF_B1 + t] = pb1[SI * 64 + t];
    }
    uint32_t bw2[2][4][2];
#pragma unroll
    for (int nl = 0; nl < 2; nl++)
#pragma unroll
        for (int ks = 0; ks < 4; ks++) {
            uint2 v = *(const uint2*)(g_w2b + SI * 4096 +
                                      (((2 * ng + nl) * 4 + ks) * 32 + lane) * 2);
            bw2[nl][ks][0] = v.x;
            bw2[nl][ks][1] = v.y;
        }
    float b2e[2], b2o[2];
#pragma unroll
    for (int nl = 0; nl < 2; nl++) {
        int n0 = ng * 16 + nl * 8 + (lane & 3) * 2;
        b2e[nl] = pb2[SI * 128 + n0];
        b2o[nl] = pb2[SI * 128 + n0 + 1];
    }
    const float b3v = pb3[SI * 256 + ng * 32 + lane];

    // prologue gather (tile = bid)
    if (t < TROWS) {
        const int p = bid * PTS + t / S, j = t % S;
        long long gi = is64 ? ((const long long*)nbr)[(size_t)p * KNN + j]
                            : (long long)((const int*)nbr)[p * KNN + j];
        const float* q = points + gi * 3;
        const float* c = points + (long long)p * 3;
        sm[PF_NB + t * 4 + 0] = q[0] - c[0];
        sm[PF_NB + t * 4 + 1] = q[1] - c[1];
        sm[PF_NB + t * 4 + 2] = q[2] - c[2];
    }
    __syncthreads();
    // prologue L1
#pragma unroll
    for (int ii = 0; ii < 10; ii++) {
        int i = t + ii * 512;
        int d2 = i & 31, r = i >> 5, d = d2 * 2;
        float v0 = sm[PF_B1 + d] + sm[PF_NB + r * 4] * sm[PF_W1 + d] +
                   sm[PF_NB + r * 4 + 1] * sm[PF_W1 + 64 + d] +
                   sm[PF_NB + r * 4 + 2] * sm[PF_W1 + 128 + d];
        float v1 = sm[PF_B1 + d + 1] + sm[PF_NB + r * 4] * sm[PF_W1 + d + 1] +
                   sm[PF_NB + r * 4 + 1] * sm[PF_W1 + 64 + d + 1] +
                   sm[PF_NB + r * 4 + 2] * sm[PF_W1 + 128 + d + 1];
        smu[PF_H1F + ((r >> 4) * 4 + (d2 >> 3)) * 128 + ((r & 7) * 4 + (d2 & 3)) * 4 +
            (((r & 8) >> 3) | ((d2 & 4) >> 1))] = packbf(lrelu(v0), lrelu(v1));
    }
    __syncthreads();

    for (int tile = bid; tile < NT; tile += nblk) {
        const int pt0 = tile * PTS;
        const bool pf = (t < TROWS) && (tile + nblk < NT);

        long long gi_n = 0;
        int pn = 0;
        if (pf) {
            pn = (tile + nblk) * PTS + t / S;
            int j = t % S;
            gi_n = is64 ? ((const long long*)nbr)[(size_t)pn * KNN + j]
                        : (long long)((const int*)nbr)[pn * KNN + j];
        }

        // ---- L2 mma: 5 mt of this half ----
        float acc2[5][2][4];
#pragma unroll
        for (int im = 0; im < 5; im++)
#pragma unroll
            for (int nl = 0; nl < 2; nl++)
#pragma unroll
                for (int e = 0; e < 4; e++) acc2[im][nl][e] = 0.f;
        const uint4* h1u4 = (const uint4*)(smu + PF_H1F);
#pragma unroll
        for (int ks = 0; ks < 4; ks++)
#pragma unroll
            for (int im = 0; im < 5; im++) {
                int mta = mg * 5 + im;
                uint4 A = h1u4[(mta * 4 + ks) * 32 + lane];
                mma16(acc2[im][0], A, bw2[0][ks][0], bw2[0][ks][1]);
                mma16(acc2[im][1], A, bw2[1][ks][0], bw2[1][ks][1]);
            }
        // ---- L2 epilogue -> H2F (own-half blocks only) ----
        {
            uint4* h2u4 = (uint4*)(smu + PF_H2F);
#pragma unroll
            for (int im = 0; im < 5; im++) {
                int mta = mg * 5 + im;
                uint4 v;
                v.x = packbf(lrelu(acc2[im][0][0] + b2e[0]), lrelu(acc2[im][0][1] + b2o[0]));
                v.y = packbf(lrelu(acc2[im][0][2] + b2e[0]), lrelu(acc2[im][0][3] + b2o[0]));
                v.z = packbf(lrelu(acc2[im][1][0] + b2e[1]), lrelu(acc2[im][1][1] + b2o[1]));
                v.w = packbf(lrelu(acc2[im][1][2] + b2e[1]), lrelu(acc2[im][1][3] + b2o[1]));
                h2u4[(mta * 8 + ng) * 32 + lane] = v;
            }
        }
        BAR_MG(1 + mg);  // H2F half-slices are mg-private

        float d0 = 0.f, d1 = 0.f, d2 = 0.f;
        if (pf) {
            const float* q = points + gi_n * 3;
            const float* c = points + (long long)pn * 3;
            d0 = q[0] - c[0];
            d1 = q[1] - c[1];
            d2 = q[2] - c[2];
        }

        // ---- L3 mma ----
        float acc3[5][4][4];
#pragma unroll
        for (int im = 0; im < 5; im++)
#pragma unroll
            for (int nq = 0; nq < 4; nq++)
#pragma unroll
                for (int e = 0; e < 4; e++) acc3[im][nq][e] = 0.f;
        const uint4* w3u4 = (const uint4*)(smu + PF_W3F);
        const uint4* h2u4 = (const uint4*)(smu + PF_H2F);
#pragma unroll
        for (int ks = 0; ks < 8; ks++) {
            int base = ((ng * 8 + ks) * 2) * 32 + lane;
            uint4 b01 = w3u4[base];
            uint4 b23 = w3u4[base + 32];
#pragma unroll
            for (int im = 0; im < 5; im++) {
                int mta = mg * 5 + im;
                uint4 A = h2u4[(mta * 8 + ks) * 32 + lane];
                mma16(acc3[im][0], A, b01.x, b01.y);
                mma16(acc3[im][1], A, b01.z, b01.w);
                mma16(acc3[im][2], A, b23.x, b23.y);
                mma16(acc3[im][3], A, b23.z, b23.w);
            }
        }

        // ---- stage + in-register pooled max; direct bf16 feats write ----
        {
            float* stg = sm + PF_STG + w * 528;
            float cur = NEGINF;
#pragma unroll
            for (int im = 0; im < 5; im++) {
                __syncwarp();
#pragma unroll
                for (int nq = 0; nq < 4; nq++)
#pragma unroll
                    for (int e = 0; e < 4; e++) {
                        int mr = (lane >> 2) + ((e >> 1) << 3);
                        int nc = nq * 8 + ((lane & 3) << 1) + (e & 1);
                        stg[mr * 33 + nc] = acc3[im][nq][e];
                    }
                __syncwarp();
#pragma unroll
                for (int r = 0; r < 16; r++) {
                    cur = fmaxf(cur, stg[r * 33 + lane]);
                    if (((im * 16 + r + 1) % S) == 0) {
                        int pt = mg * (80 / S) + (im * 16 + r) / S;
                        float val = cur + b3v;
                        float oth = __shfl_xor_sync(0xffffffffu, val, 1);
                        if (!(lane & 1))
                            g_featsb[(size_t)(pt0 + pt) * 384 + SI * 128 + ng * 16 +
                                     (lane >> 1)] = packbf(val, oth);  // FIX: SI*128
                        cur = NEGINF;
                    }
                }
            }
        }
        if (pf) {
            sm[PF_NB + t * 4 + 0] = d0;
            sm[PF_NB + t * 4 + 1] = d1;
            sm[PF_NB + t * 4 + 2] = d2;
        }
        __syncthreads();  // B3

        // ---- L1 for next tile ----
        if (tile + nblk < NT) {
#pragma unroll
            for (int ii = 0; ii < 10; ii++) {
                int i = t + ii * 512;
                int dd2 = i & 31, r = i >> 5, d = dd2 * 2;
                float v0 = sm[PF_B1 + d] + sm[PF_NB + r * 4] * sm[PF_W1 + d] +
                           sm[PF_NB + r * 4 + 1] * sm[PF_W1 + 64 + d] +
                           sm[PF_NB + r * 4 + 2] * sm[PF_W1 + 128 + d];
                float v1 = sm[PF_B1 + d + 1] + sm[PF_NB + r * 4] * sm[PF_W1 + d + 1] +
                           sm[PF_NB + r * 4 + 1] * sm[PF_W1 + 64 + d + 1] +
                           sm[PF_NB + r * 4 + 2] * sm[PF_W1 + 128 + d + 1];
                smu[PF_H1F + ((r >> 4) * 4 + (dd2 >> 3)) * 128 + ((r & 7) * 4 + (dd2 & 3)) * 4 +
                    (((r & 8) >> 3) | ((dd2 & 4) >> 1))] = packbf(lrelu(v0), lrelu(v1));
            }
        }
        __syncthreads();  // B4
    }
}

__global__ void __launch_bounds__(512) patch_all_kernel(
    const float* __restrict__ points, const void* __restrict__ nbr,
    const float* __restrict__ pb1, const float* __restrict__ pb2,
    const float* __restrict__ pb3) {
    extern __shared__ float sm[];
    int b = blockIdx.x;
    if (b < 42)       patch_run<0>(sm, b,       42,  points, nbr, pb1, pb2, pb3);
    else if (b < 127) patch_run<1>(sm, b - 42,  85,  points, nbr, pb1, pb2, pb3);
    else              patch_run<2>(sm, b - 127, 169, points, nbr, pb1, pb2, pb3);
}

// ======================= shared MLP: bf16 mma (R9 proven; bf16 feats load) =============
#define MF_A   0
#define MF_H1F 4096
#define MF_H3  4096
#define MF_H4  8256
#define MF_SB1 12288
#define MF_SB2 12544
#define MF_SB3 12672
#define MF_SB4 12736
#define MF_W5  12768
#define MF_W4  12800
#define MF_TOT 14848
#define SMEM_MLP (MF_TOT * 4)

__global__ void __launch_bounds__(256, 2) mlp_kernel(
    const float* __restrict__ sb1, const float* __restrict__ sb2,
    const float* __restrict__ sb3, const float* __restrict__ sb4,
    const float* __restrict__ sw5, const float* __restrict__ sb5,
    float* __restrict__ out) {
    extern __shared__ float sm[];
    uint32_t* smu = (uint32_t*)sm;
    const int t = threadIdx.x;
    const int w = t >> 5, lane = t & 31;
    const int pt0 = blockIdx.x * 64;

    for (int i = t; i < 2048; i += 256) sm[MF_W4 + i] = g_sw4T[i];
    if (t < 256) sm[MF_SB1 + t] = sb1[t];
    if (t < 128) sm[MF_SB2 + t] = sb2[t];
    if (t < 64) sm[MF_SB3 + t] = sb3[t];
    if (t < 32) {
        sm[MF_SB4 + t] = sb4[t];
        sm[MF_W5 + t] = sw5[t];
    }
    __syncthreads();

    float acc1[4][4][4];
#pragma unroll
    for (int mt = 0; mt < 4; mt++)
#pragma unroll
        for (int nt = 0; nt < 4; nt++)
#pragma unroll
            for (int e = 0; e < 4; e++) acc1[mt][nt][e] = 0.f;

    for (int c = 0; c < 6; c++) {
#pragma unroll
        for (int ii = 0; ii < 16; ii++) {
            int i = ii * 256 + t;
            int reg = i & 3, ln = (i >> 2) & 31, ksl = (i >> 7) & 7, mt = i >> 10;
            int row = (ln >> 2) + 8 * (reg & 1);
            int kpair = ksl * 8 + (ln & 3) + 4 * (reg >> 1);
            int p = pt0 + mt * 16 + row;
            if (p >= NPTS) p = NPTS - 1;
            smu[MF_A + i] = g_featsb[(size_t)p * 384 + c * 64 + kpair];
        }
        __syncthreads();
        const uint2* w1b = (const uint2*)g_sw1b;
        const uint4* au4 = (const uint4*)(smu + MF_A);
#pragma unroll
        for (int ksl = 0; ksl < 8; ksl++) {
            uint2 b[4];
#pragma unroll
            for (int nt = 0; nt < 4; nt++)
                b[nt] = w1b[((w * 4 + nt) * 48 + c * 8 + ksl) * 32 + lane];
#pragma unroll
            for (int mt = 0; mt < 4; mt++) {
                uint4 A = au4[(mt * 8 + ksl) * 32 + lane];
#pragma unroll
                for (int nt = 0; nt < 4; nt++) mma16(acc1[mt][nt], A, b[nt].x, b[nt].y);
            }
        }
        __syncthreads();
    }
#pragma unroll
    for (int mt = 0; mt < 4; mt++)
#pragma unroll
        for (int nt = 0; nt < 4; nt++) {
            int n0 = (w * 4 + nt) * 8 + (lane & 3) * 2;
            float be = sm[MF_SB1 + n0], bo = sm[MF_SB1 + n0 + 1];
            uint32_t lo = packbf(lrelu(acc1[mt][nt][0] + be), lrelu(acc1[mt][nt][1] + bo));
            uint32_t hi = packbf(lrelu(acc1[mt][nt][2] + be), lrelu(acc1[mt][nt][3] + bo));
            int kp = (w * 4 + nt) * 4 + (lane & 3);
            int ks = kp >> 3, kpf = kp & 7;
            int lanep = (lane >> 2) * 4 + (kpf & 3);
            int r0 = (kpf & 4) >> 1;
            *(uint2*)(smu + MF_H1F + (mt * 16 + ks) * 128 + lanep * 4 + r0) =
                make_uint2(lo, hi);
        }
    __syncthreads();

    float acc2[4][2][4];
#pragma unroll
    for (int mt = 0; mt < 4; mt++)
#pragma unroll
        for (int j = 0; j < 2; j++)
#pragma unroll
            for (int e = 0; e < 4; e++) acc2[mt][j][e] = 0.f;
    {
        const uint2* w2b = (const uint2*)g_sw2b;
        const uint4* au4 = (const uint4*)(smu + MF_H1F);
#pragma unroll 4
        for (int ks = 0; ks < 16; ks++) {
            uint2 b0 = w2b[(w * 16 + ks) * 32 + lane];
            uint2 b1 = w2b[((w + 8) * 16 + ks) * 32 + lane];
#pragma unroll
            for (int mt = 0; mt < 4; mt++) {
                uint4 A = au4[(mt * 16 + ks) * 32 + lane];
                mma16(acc2[mt][0], A, b0.x, b0.y);
                mma16(acc2[mt][1], A, b1.x, b1.y);
            }
        }
    }
    __syncthreads();
#pragma unroll
    for (int mt = 0; mt < 4; mt++)
#pragma unroll
        for (int j = 0; j < 2; j++) {
            int n0 = (w + j * 8) * 8 + (lane & 3) * 2;
            float be = sm[MF_SB2 + n0], bo = sm[MF_SB2 + n0 + 1];
            uint32_t lo = packbf(lrelu(acc2[mt][j][0] + be), lrelu(acc2[mt][j][1] + bo));
            uint32_t hi = packbf(lrelu(acc2[mt][j][2] + be), lrelu(acc2[mt][j][3] + bo));
            int kp = (w + j * 8) * 4 + (lane & 3);
            int ks = kp >> 3, kpf = kp & 7;
            int lanep = (lane >> 2) * 4 + (kpf & 3);
            int r0 = (kpf & 4) >> 1;
            *(uint2*)(smu + MF_A + (mt * 8 + ks) * 128 + lanep * 4 + r0) = make_uint2(lo, hi);
        }
    __syncthreads();

    float acc3[4][4];
#pragma unroll
    for (int mt = 0; mt < 4; mt++)
#pragma unroll
        for (int e = 0; e < 4; e++) acc3[mt][e] = 0.f;
    {
        const uint2* w3b = (const uint2*)g_sw3b;
        const uint4* au4 = (const uint4*)(smu + MF_A);
#pragma unroll
        for (int ks = 0; ks < 8; ks++) {
            uint2 b = w3b[(w * 8 + ks) * 32 + lane];
#pragma unroll
            for (int mt = 0; mt < 4; mt++) {
                uint4 A = au4[(mt * 8 + ks) * 32 + lane];
                mma16(acc3[mt], A, b.x, b.y);
            }
        }
    }
    __syncthreads();
#pragma unroll
    for (int mt = 0; mt < 4; mt++)
#pragma unroll
        for (int e = 0; e < 4; e++) {
            int m = mt * 16 + (lane >> 2) + ((e >> 1) << 3);
            int n = w * 8 + ((lane & 3) << 1) + (e & 1);
            sm[MF_H3 + m * 65 + n] = lrelu(acc3[mt][e] + sm[MF_SB3 + n]);
        }
    __syncthreads();

#pragma unroll
    for (int ii = 0; ii < 8; ii++) {
        int idx = t + ii * 256;
        int m = idx >> 5, d = idx & 31;
        float a = sm[MF_SB4 + d];
#pragma unroll 8
        for (int k = 0; k < 64; k++) a += sm[MF_H3 + m * 65 + k] * sm[MF_W4 + k * 32 + d];
        sm[MF_H4 + m * 33 + d] = lrelu(a);
    }
    __syncthreads();

    if (t < 64) {
        float s = __ldg(sb5);
#pragma unroll
        for (int k = 0; k < 32; k++) s += sm[MF_H4 + t * 33 + k] * sm[MF_W5 + k];
        int p = pt0 + t;
        if (p < NPTS) out[p] = s;
    }
}

// ======================= launch ========================================================
extern "C" void kernel_launch(void* const* d_in, const int* in_sizes, int n_in,
                              void* d_out, int out_size) {
    (void)out_size;
    const int want[18] = {300000, 2000000, 576, 192, 24576, 384, 98304, 768,
                          196608, 256,    32768, 128, 8192, 64,  2048,  32, 32, 1};
    const void* ptr[18] = {};
    {
        int used[64] = {};
        for (int w = 0; w < 18; w++) {
            for (int i = 0; i < n_in && i < 64; i++) {
                if (!used[i] && in_sizes[i] == want[w]) {
                    ptr[w] = d_in[i];
                    used[i] = 1;
                    break;
                }
            }
        }
        for (int w = 0; w < 18; w++)
            if (!ptr[w] && w < n_in) ptr[w] = d_in[w];
    }

    const float* points = (const float*)ptr[0];
    const void*  nbr    = ptr[1];
    const float* pw1 = (const float*)ptr[2];
    const float* pb1 = (const float*)ptr[3];
    const float* pw2 = (const float*)ptr[4];
    const float* pb2 = (const float*)ptr[5];
    const float* pw3 = (const float*)ptr[6];
    const float* pb3 = (const float*)ptr[7];
    const float* sw1 = (const float*)ptr[8];
    const float* sb1 = (const float*)ptr[9];
    const float* sw2 = (const float*)ptr[10];
    const float* sb2 = (const float*)ptr[11];
    const float* sw3 = (const float*)ptr[12];
    const float* sb3 = (const float*)ptr[13];
    const float* sw4 = (const float*)ptr[14];
    const float* sb4 = (const float*)ptr[15];
    const float* sw5 = (const float*)ptr[16];
    const float* sb5 = (const float*)ptr[17];

    cudaFuncSetAttribute(patch_all_kernel, cudaFuncAttributeMaxDynamicSharedMemorySize,
                         SMEM_PATCH);
    cudaFuncSetAttribute(mlp_kernel, cudaFuncAttributeMaxDynamicSharedMemorySize, SMEM_MLP);

    detect_kernel<<<1, 256>>>((const unsigned int*)nbr);
    prep_kernel<<<128, 256>>>(pw1, pw2, pw3, sw1, sw2, sw3, sw4);
    patch_all_kernel<<<296, 512, SMEM_PATCH>>>(points, nbr, pb1, pb2, pb3);
    mlp_kernel<<<(NPTS + 63) / 64, 256, SMEM_MLP>>>(sb1, sb2, sb3, sb4, sw5, sb5,
                                                    (float*)d_out);
}

// round 12
// speedup vs baseline: 3.7023x; 1.2826x over previous
#include <cuda_runtime.h>
#include <cstddef>
#include <cstdint>

#define NPTS 100000
#define KNN 20
#define NEGINF -3.4e38f

__device__ __forceinline__ float lrelu(float x) { return fmaxf(x, 0.2f * x); }
__device__ __forceinline__ uint32_t packbf(float lo, float hi) {
    uint32_t r;
    asm("cvt.rn.bf16x2.f32 %0, %1, %2;" : "=r"(r) : "f"(hi), "f"(lo));
    return r;
}
__device__ __forceinline__ void mma16(float* d, const uint4& a, uint32_t b0, uint32_t b1) {
    asm volatile(
        "mma.sync.aligned.m16n8k16.row.col.f32.bf16.bf16.f32 "
        "{%0,%1,%2,%3}, {%4,%5,%6,%7}, {%8,%9}, {%0,%1,%2,%3};"
        : "+f"(d[0]), "+f"(d[1]), "+f"(d[2]), "+f"(d[3])
        : "r"(a.x), "r"(a.y), "r"(a.z), "r"(a.w), "r"(b0), "r"(b1));
}
#define BAR_MG(id) asm volatile("bar.sync %0, 256;" ::"r"(id) : "memory")

// ======================= device scratch ================================================
__device__ int      g_idx64;
__device__ float    g_w1T[3 * 3 * 64];
__device__ uint32_t g_w2b[3 * 4096];       // patch W2 bf16 B-frags
__device__ uint32_t g_w3b[3 * 16384];      // patch W3 bf16 B-frags, pair-major
__device__ uint32_t g_sw1b[32 * 48 * 64];  // MLP bf16 B-frags
__device__ uint32_t g_sw2b[16 * 16 * 64];
__device__ uint32_t g_sw3b[8 * 8 * 64];
__device__ float    g_sw4T[64 * 32];
__device__ uint32_t g_featsb[(size_t)NPTS * 384];  // feats as bf16x2 pairs

__global__ void detect_kernel(const unsigned int* __restrict__ raw) {
    __shared__ int flag;
    if (threadIdx.x == 0) flag = 0;
    __syncthreads();
    if (raw[2 * threadIdx.x + 1] != 0u) atomicOr(&flag, 1);
    __syncthreads();
    if (threadIdx.x == 0) g_idx64 = (flag == 0) ? 1 : 0;
}

__global__ void prep_kernel(const float* __restrict__ pw1, const float* __restrict__ pw2,
                            const float* __restrict__ pw3, const float* __restrict__ sw1,
                            const float* __restrict__ sw2, const float* __restrict__ sw3,
                            const float* __restrict__ sw4) {
    const int tid = blockIdx.x * blockDim.x + threadIdx.x;
    const int stride = gridDim.x * blockDim.x;
    for (int i = tid; i < 3 * 3 * 64; i += stride) {
        int s = i / 192, r = i % 192, c = r / 64, d = r % 64;
        g_w1T[i] = pw1[s * 192 + d * 3 + c];
    }
    for (int i = tid; i < 3 * 128 * 32; i += stride) {
        int s = i / 4096, r = i % 4096, n = r >> 5, k2 = r & 31, k = k2 * 2;
        float v0 = pw2[s * 8192 + n * 64 + k];
        float v1 = pw2[s * 8192 + n * 64 + k + 1];
        int idx = (((n >> 3) * 4 + (k2 >> 3)) * 32 + (n & 7) * 4 + (k2 & 3)) * 2 +
                  ((k2 >> 2) & 1);
        g_w2b[s * 4096 + idx] = packbf(v0, v1);
    }
    for (int i = tid; i < 3 * 256 * 64; i += stride) {
        int s = i >> 14, r = i & 16383, n = r >> 6, k2 = r & 63, k = k2 * 2;
        float v0 = pw3[s * 32768 + n * 128 + k];
        float v1 = pw3[s * 32768 + n * 128 + k + 1];
        int ng = n >> 5, nq = (n >> 3) & 3, pair = nq >> 1, nqi = nq & 1;
        int ks = k2 >> 3, reg = (k2 >> 2) & 1, lane = (n & 7) * 4 + (k2 & 3);
        int idx = ((((ng * 8 + ks) * 2 + pair) * 32 + lane) * 4) + nqi * 2 + reg;
        g_w3b[s * 16384 + idx] = packbf(v0, v1);
    }
    for (int i = tid; i < 256 * 384; i += stride) {
        int n = i / 384, kp = i % 384;
        int ks = kp >> 3, k2 = kp & 7;
        int idx = ((n >> 3) * 48 + ks) * 64 + ((n & 7) * 4 + (k2 & 3)) * 2 + ((k2 >> 2) & 1);
        g_sw1b[idx] = packbf(sw1[n * 768 + 2 * kp], sw1[n * 768 + 2 * kp + 1]);
    }
    for (int i = tid; i < 128 * 128; i += stride) {
        int n = i >> 7, kp = i & 127;
        int ks = kp >> 3, k2 = kp & 7;
        int idx = ((n >> 3) * 16 + ks) * 64 + ((n & 7) * 4 + (k2 & 3)) * 2 + ((k2 >> 2) & 1);
        g_sw2b[idx] = packbf(sw2[n * 256 + 2 * kp], sw2[n * 256 + 2 * kp + 1]);
    }
    for (int i = tid; i < 64 * 64; i += stride) {
        int n = i >> 6, kp = i & 63;
        int ks = kp >> 3, k2 = kp & 7;
        int idx = ((n >> 3) * 8 + ks) * 64 + ((n & 7) * 4 + (k2 & 3)) * 2 + ((k2 >> 2) & 1);
        g_sw3b[idx] = packbf(sw3[n * 128 + 2 * kp], sw3[n * 128 + 2 * kp + 1]);
    }
    for (int i = tid; i < 64 * 32; i += stride) {
        int k = i >> 5, d = i & 31;
        g_sw4T[i] = sw4[d * 64 + k];
    }
}

// ======================= patch stage: 160-row supertile, bf16 ==========================
#define PF_W3F  0        // 16384
#define PF_H2F  16384    // 10240
#define PF_STG  26624    // 16 warps * 320 u32 (stride-20, bf16x2) = 5120
#define PF_H1F  35072    // 5120
#define PF_NB   40192    // 640
#define PF_W1   40832    // 192
#define PF_B1   41024    // 64
#define PF_TOT  41088
#define SMEM_PATCH (PF_TOT * 4)
#define TROWS 160

template <int SI>
__device__ __forceinline__ void patch_run(
    float* sm, int bid, int nblk,
    const float* __restrict__ points, const void* __restrict__ nbr,
    const float* __restrict__ pb1, const float* __restrict__ pb2,
    const float* __restrict__ pb3) {
    constexpr int S = (SI == 0) ? 5 : (SI == 1 ? 10 : 20);
    constexpr int PTS = TROWS / S;
    constexpr int NT = NPTS / PTS;

    uint32_t* smu = (uint32_t*)sm;
    const int t = threadIdx.x;
    const int w = t >> 5, lane = t & 31;
    const int ng = w & 7, mg = w >> 3;   // mg: mt half {0..4} / {5..9}
    const int is64 = g_idx64;

    {
        const uint4* src = (const uint4*)g_w3b + SI * 4096;
        uint4* dst = (uint4*)(smu + PF_W3F);
        for (int i = t; i < 4096; i += 512) dst[i] = src[i];
        for (int i = t; i < 192; i += 512) sm[PF_W1 + i] = g_w1T[SI * 192 + i];
        if (t < 64) sm[PF_B1 + t] = pb1[SI * 64 + t];
    }
    uint32_t bw2[2][4][2];
#pragma unroll
    for (int nl = 0; nl < 2; nl++)
#pragma unroll
        for (int ks = 0; ks < 4; ks++) {
            uint2 v = *(const uint2*)(g_w2b + SI * 4096 +
                                      (((2 * ng + nl) * 4 + ks) * 32 + lane) * 2);
            bw2[nl][ks][0] = v.x;
            bw2[nl][ks][1] = v.y;
        }
    float b2e[2], b2o[2];
#pragma unroll
    for (int nl = 0; nl < 2; nl++) {
        int n0 = ng * 16 + nl * 8 + (lane & 3) * 2;
        b2e[nl] = pb2[SI * 128 + n0];
        b2o[nl] = pb2[SI * 128 + n0 + 1];
    }
    // scan-lane dim mapping: cp = lane>>1, dim = ng*32 + 8*(cp>>2) + 2*(cp&3) + (lane&1)
    const float b3v =
        pb3[SI * 256 + ng * 32 + 8 * ((lane >> 1) >> 2) + 2 * ((lane >> 1) & 3) + (lane & 1)];

    // prologue gather (tile = bid)
    if (t < TROWS) {
        const int p = bid * PTS + t / S, j = t % S;
        long long gi = is64 ? ((const long long*)nbr)[(size_t)p * KNN + j]
                            : (long long)((const int*)nbr)[p * KNN + j];
        const float* q = points + gi * 3;
        const float* c = points + (long long)p * 3;
        sm[PF_NB + t * 4 + 0] = q[0] - c[0];
        sm[PF_NB + t * 4 + 1] = q[1] - c[1];
        sm[PF_NB + t * 4 + 2] = q[2] - c[2];
    }
    __syncthreads();
    // prologue L1
#pragma unroll
    for (int ii = 0; ii < 10; ii++) {
        int i = t + ii * 512;
        int d2 = i & 31, r = i >> 5, d = d2 * 2;
        float v0 = sm[PF_B1 + d] + sm[PF_NB + r * 4] * sm[PF_W1 + d] +
                   sm[PF_NB + r * 4 + 1] * sm[PF_W1 + 64 + d] +
                   sm[PF_NB + r * 4 + 2] * sm[PF_W1 + 128 + d];
        float v1 = sm[PF_B1 + d + 1] + sm[PF_NB + r * 4] * sm[PF_W1 + d + 1] +
                   sm[PF_NB + r * 4 + 1] * sm[PF_W1 + 64 + d + 1] +
                   sm[PF_NB + r * 4 + 2] * sm[PF_W1 + 128 + d + 1];
        smu[PF_H1F + ((r >> 4) * 4 + (d2 >> 3)) * 128 + ((r & 7) * 4 + (d2 & 3)) * 4 +
            (((r & 8) >> 3) | ((d2 & 4) >> 1))] = packbf(lrelu(v0), lrelu(v1));
    }
    __syncthreads();

    for (int tile = bid; tile < NT; tile += nblk) {
        const int pt0 = tile * PTS;
        const bool pf = (t < TROWS) && (tile + nblk < NT);

        long long gi_n = 0;
        int pn = 0;
        if (pf) {
            pn = (tile + nblk) * PTS + t / S;
            int j = t % S;
            gi_n = is64 ? ((const long long*)nbr)[(size_t)pn * KNN + j]
                        : (long long)((const int*)nbr)[pn * KNN + j];
        }

        // ---- L2 mma: 5 mt of this half ----
        float acc2[5][2][4];
#pragma unroll
        for (int im = 0; im < 5; im++)
#pragma unroll
            for (int nl = 0; nl < 2; nl++)
#pragma unroll
                for (int e = 0; e < 4; e++) acc2[im][nl][e] = 0.f;
        const uint4* h1u4 = (const uint4*)(smu + PF_H1F);
#pragma unroll
        for (int ks = 0; ks < 4; ks++)
#pragma unroll
            for (int im = 0; im < 5; im++) {
                int mta = mg * 5 + im;
                uint4 A = h1u4[(mta * 4 + ks) * 32 + lane];
                mma16(acc2[im][0], A, bw2[0][ks][0], bw2[0][ks][1]);
                mma16(acc2[im][1], A, bw2[1][ks][0], bw2[1][ks][1]);
            }
        // ---- L2 epilogue -> H2F (own-half blocks only) ----
        {
            uint4* h2u4 = (uint4*)(smu + PF_H2F);
#pragma unroll
            for (int im = 0; im < 5; im++) {
                int mta = mg * 5 + im;
                uint4 v;
                v.x = packbf(lrelu(acc2[im][0][0] + b2e[0]), lrelu(acc2[im][0][1] + b2o[0]));
                v.y = packbf(lrelu(acc2[im][0][2] + b2e[0]), lrelu(acc2[im][0][3] + b2o[0]));
                v.z = packbf(lrelu(acc2[im][1][0] + b2e[1]), lrelu(acc2[im][1][1] + b2o[1]));
                v.w = packbf(lrelu(acc2[im][1][2] + b2e[1]), lrelu(acc2[im][1][3] + b2o[1]));
                h2u4[(mta * 8 + ng) * 32 + lane] = v;
            }
        }
        BAR_MG(1 + mg);  // H2F half-slices are mg-private

        float d0 = 0.f, d1 = 0.f, d2 = 0.f;
        if (pf) {
            const float* q = points + gi_n * 3;
            const float* c = points + (long long)pn * 3;
            d0 = q[0] - c[0];
            d1 = q[1] - c[1];
            d2 = q[2] - c[2];
        }

        // ---- L3 mma ----
        float acc3[5][4][4];
#pragma unroll
        for (int im = 0; im < 5; im++)
#pragma unroll
            for (int nq = 0; nq < 4; nq++)
#pragma unroll
                for (int e = 0; e < 4; e++) acc3[im][nq][e] = 0.f;
        const uint4* w3u4 = (const uint4*)(smu + PF_W3F);
        const uint4* h2u4 = (const uint4*)(smu + PF_H2F);
#pragma unroll
        for (int ks = 0; ks < 8; ks++) {
            int base = ((ng * 8 + ks) * 2) * 32 + lane;
            uint4 b01 = w3u4[base];
            uint4 b23 = w3u4[base + 32];
#pragma unroll
            for (int im = 0; im < 5; im++) {
                int mta = mg * 5 + im;
                uint4 A = h2u4[(mta * 8 + ks) * 32 + lane];
                mma16(acc3[im][0], A, b01.x, b01.y);
                mma16(acc3[im][1], A, b01.z, b01.w);
                mma16(acc3[im][2], A, b23.x, b23.y);
                mma16(acc3[im][3], A, b23.z, b23.w);
            }
        }

        // ---- bf16 staging (stride 20, conflict-free) + broadcast scan + feats write ----
        {
            uint32_t* stg = smu + PF_STG + w * 320;
            float cur = NEGINF;
#pragma unroll
            for (int im = 0; im < 5; im++) {
                __syncwarp();
#pragma unroll
                for (int nq = 0; nq < 4; nq++) {
                    // rows (lane>>2) and (lane>>2)+8 ; columns nq*8+(lane&3)*2 .. +1
                    uint32_t lo = packbf(acc3[im][nq][0], acc3[im][nq][1]);
                    uint32_t hi = packbf(acc3[im][nq][2], acc3[im][nq][3]);
                    int cp = nq * 4 + (lane & 3);
                    stg[(lane >> 2) * 20 + cp] = lo;
                    stg[((lane >> 2) + 8) * 20 + cp] = hi;
                }
                __syncwarp();
#pragma unroll
                for (int r = 0; r < 16; r++) {
                    uint32_t u = stg[r * 20 + (lane >> 1)];  // 2-lane broadcast
                    float v = __uint_as_float((lane & 1) ? (u & 0xffff0000u) : (u << 16));
                    cur = fmaxf(cur, v);
                    if (((im * 16 + r + 1) % S) == 0) {
                        int pt = mg * (80 / S) + (im * 16 + r) / S;
                        float val = cur + b3v;
                        float oth = __shfl_xor_sync(0xffffffffu, val, 1);
                        if (!(lane & 1))
                            g_featsb[(size_t)(pt0 + pt) * 384 + SI * 128 + ng * 16 +
                                     (lane >> 1)] = packbf(val, oth);
                        cur = NEGINF;
                    }
                }
            }
        }
        if (pf) {
            sm[PF_NB + t * 4 + 0] = d0;
            sm[PF_NB + t * 4 + 1] = d1;
            sm[PF_NB + t * 4 + 2] = d2;
        }
        __syncthreads();  // B3

        // ---- L1 for next tile ----
        if (tile + nblk < NT) {
#pragma unroll
            for (int ii = 0; ii < 10; ii++) {
                int i = t + ii * 512;
                int dd2 = i & 31, r = i >> 5, d = dd2 * 2;
                float v0 = sm[PF_B1 + d] + sm[PF_NB + r * 4] * sm[PF_W1 + d] +
                           sm[PF_NB + r * 4 + 1] * sm[PF_W1 + 64 + d] +
                           sm[PF_NB + r * 4 + 2] * sm[PF_W1 + 128 + d];
                float v1 = sm[PF_B1 + d + 1] + sm[PF_NB + r * 4] * sm[PF_W1 + d + 1] +
                           sm[PF_NB + r * 4 + 1] * sm[PF_W1 + 64 + d + 1] +
                           sm[PF_NB + r * 4 + 2] * sm[PF_W1 + 128 + d + 1];
                smu[PF_H1F + ((r >> 4) * 4 + (dd2 >> 3)) * 128 + ((r & 7) * 4 + (dd2 & 3)) * 4 +
                    (((r & 8) >> 3) | ((dd2 & 4) >> 1))] = packbf(lrelu(v0), lrelu(v1));
            }
        }
        __syncthreads();  // B4
    }
}

__global__ void __launch_bounds__(512) patch_all_kernel(
    const float* __restrict__ points, const void* __restrict__ nbr,
    const float* __restrict__ pb1, const float* __restrict__ pb2,
    const float* __restrict__ pb3) {
    extern __shared__ float sm[];
    int b = blockIdx.x;
    if (b < 42)       patch_run<0>(sm, b,       42,  points, nbr, pb1, pb2, pb3);
    else if (b < 127) patch_run<1>(sm, b - 42,  85,  points, nbr, pb1, pb2, pb3);
    else              patch_run<2>(sm, b - 127, 169, points, nbr, pb1, pb2, pb3);
}

// ======================= shared MLP: bf16 mma (R11 proven) =============================
#define MF_A   0
#define MF_H1F 4096
#define MF_H3  4096
#define MF_H4  8256
#define MF_SB1 12288
#define MF_SB2 12544
#define MF_SB3 12672
#define MF_SB4 12736
#define MF_W5  12768
#define MF_W4  12800
#define MF_TOT 14848
#define SMEM_MLP (MF_TOT * 4)

__global__ void __launch_bounds__(256, 2) mlp_kernel(
    const float* __restrict__ sb1, const float* __restrict__ sb2,
    const float* __restrict__ sb3, const float* __restrict__ sb4,
    const float* __restrict__ sw5, const float* __restrict__ sb5,
    float* __restrict__ out) {
    extern __shared__ float sm[];
    uint32_t* smu = (uint32_t*)sm;
    const int t = threadIdx.x;
    const int w = t >> 5, lane = t & 31;
    const int pt0 = blockIdx.x * 64;

    for (int i = t; i < 2048; i += 256) sm[MF_W4 + i] = g_sw4T[i];
    if (t < 256) sm[MF_SB1 + t] = sb1[t];
    if (t < 128) sm[MF_SB2 + t] = sb2[t];
    if (t < 64) sm[MF_SB3 + t] = sb3[t];
    if (t < 32) {
        sm[MF_SB4 + t] = sb4[t];
        sm[MF_W5 + t] = sw5[t];
    }
    __syncthreads();

    float acc1[4][4][4];
#pragma unroll
    for (int mt = 0; mt < 4; mt++)
#pragma unroll
        for (int nt = 0; nt < 4; nt++)
#pragma unroll
            for (int e = 0; e < 4; e++) acc1[mt][nt][e] = 0.f;

    for (int c = 0; c < 6; c++) {
#pragma unroll
        for (int ii = 0; ii < 16; ii++) {
            int i = ii * 256 + t;
            int reg = i & 3, ln = (i >> 2) & 31, ksl = (i >> 7) & 7, mt = i >> 10;
            int row = (ln >> 2) + 8 * (reg & 1);
            int kpair = ksl * 8 + (ln & 3) + 4 * (reg >> 1);
            int p = pt0 + mt * 16 + row;
            if (p >= NPTS) p = NPTS - 1;
            smu[MF_A + i] = g_featsb[(size_t)p * 384 + c * 64 + kpair];
        }
        __syncthreads();
        const uint2* w1b = (const uint2*)g_sw1b;
        const uint4* au4 = (const uint4*)(smu + MF_A);
#pragma unroll
        for (int ksl = 0; ksl < 8; ksl++) {
            uint2 b[4];
#pragma unroll
            for (int nt = 0; nt < 4; nt++)
                b[nt] = w1b[((w * 4 + nt) * 48 + c * 8 + ksl) * 32 + lane];
#pragma unroll
            for (int mt = 0; mt < 4; mt++) {
                uint4 A = au4[(mt * 8 + ksl) * 32 + lane];
#pragma unroll
                for (int nt = 0; nt < 4; nt++) mma16(acc1[mt][nt], A, b[nt].x, b[nt].y);
            }
        }
        __syncthreads();
    }
#pragma unroll
    for (int mt = 0; mt < 4; mt++)
#pragma unroll
        for (int nt = 0; nt < 4; nt++) {
            int n0 = (w * 4 + nt) * 8 + (lane & 3) * 2;
            float be = sm[MF_SB1 + n0], bo = sm[MF_SB1 + n0 + 1];
            uint32_t lo = packbf(lrelu(acc1[mt][nt][0] + be), lrelu(acc1[mt][nt][1] + bo));
            uint32_t hi = packbf(lrelu(acc1[mt][nt][2] + be), lrelu(acc1[mt][nt][3] + bo));
            int kp = (w * 4 + nt) * 4 + (lane & 3);
            int ks = kp >> 3, kpf = kp & 7;
            int lanep = (lane >> 2) * 4 + (kpf & 3);
            int r0 = (kpf & 4) >> 1;
            *(uint2*)(smu + MF_H1F + (mt * 16 + ks) * 128 + lanep * 4 + r0) =
                make_uint2(lo, hi);
        }
    __syncthreads();

    float acc2[4][2][4];
#pragma unroll
    for (int mt = 0; mt < 4; mt++)
#pragma unroll
        for (int j = 0; j < 2; j++)
#pragma unroll
            for (int e = 0; e < 4; e++) acc2[mt][j][e] = 0.f;
    {
        const uint2* w2b = (const uint2*)g_sw2b;
        const uint4* au4 = (const uint4*)(smu + MF_H1F);
#pragma unroll 4
        for (int ks = 0; ks < 16; ks++) {
            uint2 b0 = w2b[(w * 16 + ks) * 32 + lane];
            uint2 b1 = w2b[((w + 8) * 16 + ks) * 32 + lane];
#pragma unroll
            for (int mt = 0; mt < 4; mt++) {
                uint4 A = au4[(mt * 16 + ks) * 32 + lane];
                mma16(acc2[mt][0], A, b0.x, b0.y);
                mma16(acc2[mt][1], A, b1.x, b1.y);
            }
        }
    }
    __syncthreads();
#pragma unroll
    for (int mt = 0; mt < 4; mt++)
#pragma unroll
        for (int j = 0; j < 2; j++) {
            int n0 = (w + j * 8) * 8 + (lane & 3) * 2;
            float be = sm[MF_SB2 + n0], bo = sm[MF_SB2 + n0 + 1];
            uint32_t lo = packbf(lrelu(acc2[mt][j][0] + be), lrelu(acc2[mt][j][1] + bo));
            uint32_t hi = packbf(lrelu(acc2[mt][j][2] + be), lrelu(acc2[mt][j][3] + bo));
            int kp = (w + j * 8) * 4 + (lane & 3);
            int ks = kp >> 3, kpf = kp & 7;
            int lanep = (lane >> 2) * 4 + (kpf & 3);
            int r0 = (kpf & 4) >> 1;
            *(uint2*)(smu + MF_A + (mt * 8 + ks) * 128 + lanep * 4 + r0) = make_uint2(lo, hi);
        }
    __syncthreads();

    float acc3[4][4];
#pragma unroll
    for (int mt = 0; mt < 4; mt++)
#pragma unroll
        for (int e = 0; e < 4; e++) acc3[mt][e] = 0.f;
    {
        const uint2* w3b = (const uint2*)g_sw3b;
        const uint4* au4 = (const uint4*)(smu + MF_A);
#pragma unroll
        for (int ks = 0; ks < 8; ks++) {
            uint2 b = w3b[(w * 8 + ks) * 32 + lane];
#pragma unroll
            for (int mt = 0; mt < 4; mt++) {
                uint4 A = au4[(mt * 8 + ks) * 32 + lane];
                mma16(acc3[mt], A, b.x, b.y);
            }
        }
    }
    __syncthreads();
#pragma unroll
    for (int mt = 0; mt < 4; mt++)
#pragma unroll
        for (int e = 0; e < 4; e++) {
            int m = mt * 16 + (lane >> 2) + ((e >> 1) << 3);
            int n = w * 8 + ((lane & 3) << 1) + (e & 1);
            sm[MF_H3 + m * 65 + n] = lrelu(acc3[mt][e] + sm[MF_SB3 + n]);
        }
    __syncthreads();

#pragma unroll
    for (int ii = 0; ii < 8; ii++) {
        int idx = t + ii * 256;
        int m = idx >> 5, d = idx & 31;
        float a = sm[MF_SB4 + d];
#pragma unroll 8
        for (int k = 0; k < 64; k++) a += sm[MF_H3 + m * 65 + k] * sm[MF_W4 + k * 32 + d];
        sm[MF_H4 + m * 33 + d] = lrelu(a);
    }
    __syncthreads();

    if (t < 64) {
        float s = __ldg(sb5);
#pragma unroll
        for (int k = 0; k < 32; k++) s += sm[MF_H4 + t * 33 + k] * sm[MF_W5 + k];
        int p = pt0 + t;
        if (p < NPTS) out[p] = s;
    }
}

// ======================= launch ========================================================
extern "C" void kernel_launch(void* const* d_in, const int* in_sizes, int n_in,
                              void* d_out, int out_size) {
    (void)out_size;
    const int want[18] = {300000, 2000000, 576, 192, 24576, 384, 98304, 768,
                          196608, 256,    32768, 128, 8192, 64,  2048,  32, 32, 1};
    const void* ptr[18] = {};
    {
        int used[64] = {};
        for (int w = 0; w < 18; w++) {
            for (int i = 0; i < n_in && i < 64; i++) {
                if (!used[i] && in_sizes[i] == want[w]) {
                    ptr[w] = d_in[i];
                    used[i] = 1;
                    break;
                }
            }
        }
        for (int w = 0; w < 18; w++)
            if (!ptr[w] && w < n_in) ptr[w] = d_in[w];
    }

    const float* points = (const float*)ptr[0];
    const void*  nbr    = ptr[1];
    const float* pw1 = (const float*)ptr[2];
    const float* pb1 = (const float*)ptr[3];
    const float* pw2 = (const float*)ptr[4];
    const float* pb2 = (const float*)ptr[5];
    const float* pw3 = (const float*)ptr[6];
    const float* pb3 = (const float*)ptr[7];
    const float* sw1 = (const float*)ptr[8];
    const float* sb1 = (const float*)ptr[9];
    const float* sw2 = (const float*)ptr[10];
    const float* sb2 = (const float*)ptr[11];
    const float* sw3 = (const float*)ptr[12];
    const float* sb3 = (const float*)ptr[13];
    const float* sw4 = (const float*)ptr[14];
    const float* sb4 = (const float*)ptr[15];
    const float* sw5 = (const float*)ptr[16];
    const float* sb5 = (const float*)ptr[17];

    cudaFuncSetAttribute(patch_all_kernel, cudaFuncAttributeMaxDynamicSharedMemorySize,
                         SMEM_PATCH);
    cudaFuncSetAttribute(mlp_kernel, cudaFuncAttributeMaxDynamicSharedMemorySize, SMEM_MLP);

    detect_kernel<<<1, 256>>>((const unsigned int*)nbr);
    prep_kernel<<<128, 256>>>(pw1, pw2, pw3, sw1, sw2, sw3, sw4);
    patch_all_kernel<<<296, 512, SMEM_PATCH>>>(points, nbr, pb1, pb2, pb3);
    mlp_kernel<<<(NPTS + 63) / 64, 256, SMEM_MLP>>>(sb1, sb2, sb3, sb4, sw5, sb5,
                                                    (float*)d_out);
}